// round 11
// baseline (speedup 1.0000x reference)
#include <cuda_runtime.h>
#include <cuda_fp16.h>
#include <cstdint>
#include <cstddef>

#define NN 170000
#define NE 1200000
#define NBLK_SCAN 167        // ceil(NN / 1024)

// ---------------- device scratch (allocation-free) ----------------
__device__ __half g_G[(size_t)NN * 128];  // GEMM output (fp16)
__device__ __half g_H[(size_t)NN * 128];  // GEMM A source (fp16)
__device__ int    g_deg_out[NN];
__device__ int    g_cnt[NN];
__device__ int    g_off[NN];
__device__ int2   g_meta[NN];             // {offset, count}
__device__ int    g_fill[NN];
__device__ int    g_bsum[NBLK_SCAN];
__device__ float  g_norm_out[NN];
__device__ float  g_norm_in[NN];
__device__ int    g_csr_src[NE];

// ---------------- CSR build ----------------
__global__ void zero_kernel() {
    int i = blockIdx.x * blockDim.x + threadIdx.x;
    if (i < NN) { g_deg_out[i] = 0; g_cnt[i] = 0; g_fill[i] = 0; }
}

__global__ void hist_kernel(const int* __restrict__ src, const int* __restrict__ dst) {
    int e = blockIdx.x * blockDim.x + threadIdx.x;
    if (e < NE) {
        atomicAdd(&g_deg_out[src[e]], 1);
        atomicAdd(&g_cnt[dst[e]], 1);
    }
}

// norms + feat*norm_out -> g_H (fp16), fused
__global__ void norm_conv_kernel(const float* __restrict__ X) {
    int i = blockIdx.x * blockDim.x + threadIdx.x;   // over NN*32 float4s
    if (i >= NN * 32) return;
    const int row = i >> 5;
    int din  = g_cnt[row];     if (din  < 1) din  = 1;
    int dout = g_deg_out[row]; if (dout < 1) dout = 1;
    const float no = rsqrtf((float)dout);
    if ((i & 31) == 0) {
        g_norm_in[row]  = rsqrtf((float)din);
        g_norm_out[row] = no;
    }
    float4 v = reinterpret_cast<const float4*>(X)[i];
    __half2 h0 = __floats2half2_rn(v.x * no, v.y * no);
    __half2 h1 = __floats2half2_rn(v.z * no, v.w * no);
    uint2 o;
    o.x = *reinterpret_cast<uint32_t*>(&h0);
    o.y = *reinterpret_cast<uint32_t*>(&h1);
    reinterpret_cast<uint2*>(g_H)[i] = o;
}

__global__ void scan1_kernel() {
    __shared__ int sh[256];
    const int t = threadIdx.x;
    const int base = blockIdx.x * 1024 + t * 4;
    int c0 = 0, c1 = 0, c2 = 0, c3 = 0;
    if (base + 3 < NN) {
        int4 v = *reinterpret_cast<const int4*>(&g_cnt[base]);
        c0 = v.x; c1 = v.y; c2 = v.z; c3 = v.w;
    } else {
        if (base     < NN) c0 = g_cnt[base];
        if (base + 1 < NN) c1 = g_cnt[base + 1];
        if (base + 2 < NN) c2 = g_cnt[base + 2];
        if (base + 3 < NN) c3 = g_cnt[base + 3];
    }
    const int mysum = c0 + c1 + c2 + c3;
    sh[t] = mysum;
    __syncthreads();
    for (int off = 1; off < 256; off <<= 1) {
        int v = (t >= off) ? sh[t - off] : 0;
        __syncthreads();
        sh[t] += v;
        __syncthreads();
    }
    const int excl = sh[t] - mysum;
    if (t == 255) g_bsum[blockIdx.x] = sh[255];
    if (base     < NN) g_off[base]     = excl;
    if (base + 1 < NN) g_off[base + 1] = excl + c0;
    if (base + 2 < NN) g_off[base + 2] = excl + c0 + c1;
    if (base + 3 < NN) g_off[base + 3] = excl + c0 + c1 + c2;
}

__global__ void scan2_kernel() {
    __shared__ int sh[256];
    const int t = threadIdx.x;
    int v = (t < NBLK_SCAN) ? g_bsum[t] : 0;
    sh[t] = v;
    __syncthreads();
    for (int off = 1; off < 256; off <<= 1) {
        int u = (t >= off) ? sh[t - off] : 0;
        __syncthreads();
        sh[t] += u;
        __syncthreads();
    }
    if (t < NBLK_SCAN) g_bsum[t] = sh[t] - v;
}

__global__ void scan3_kernel() {
    int i = blockIdx.x * blockDim.x + threadIdx.x;
    if (i < NN) {
        const int off = g_off[i] + g_bsum[i >> 10];
        g_off[i] = off;
        g_meta[i] = make_int2(off, g_cnt[i]);
    }
}

__global__ void place_kernel(const int* __restrict__ src, const int* __restrict__ dst) {
    int e = blockIdx.x * blockDim.x + threadIdx.x;
    if (e < NE) {
        const int d = dst[e];
        const int pos = g_off[d] + atomicAdd(&g_fill[d], 1);
        g_csr_src[pos] = src[e];
    }
}

// ---------------- mma / ldmatrix / cp.async helpers ----------------
__device__ __forceinline__ void mma_f16(float* c, const uint32_t* a, uint32_t b0, uint32_t b1) {
    asm volatile(
        "mma.sync.aligned.m16n8k16.row.col.f32.f16.f16.f32 "
        "{%0,%1,%2,%3}, {%4,%5,%6,%7}, {%8,%9}, {%0,%1,%2,%3};"
        : "+f"(c[0]), "+f"(c[1]), "+f"(c[2]), "+f"(c[3])
        : "r"(a[0]), "r"(a[1]), "r"(a[2]), "r"(a[3]), "r"(b0), "r"(b1));
}

__device__ __forceinline__ void ldsm_x4(uint32_t* r, uint32_t addr) {
    asm volatile("ldmatrix.sync.aligned.m8n8.x4.shared.b16 {%0,%1,%2,%3}, [%4];"
                 : "=r"(r[0]), "=r"(r[1]), "=r"(r[2]), "=r"(r[3]) : "r"(addr));
}

__device__ __forceinline__ void ldsm_x2(uint32_t& r0, uint32_t& r1, uint32_t addr) {
    asm volatile("ldmatrix.sync.aligned.m8n8.x2.shared.b16 {%0,%1}, [%2];"
                 : "=r"(r0), "=r"(r1) : "r"(addr));
}

__device__ __forceinline__ void cp16(uint32_t dst, const void* src) {
    asm volatile("cp.async.cg.shared.global [%0], [%1], 16;" :: "r"(dst), "l"(src));
}
__device__ __forceinline__ void cp_commit() { asm volatile("cp.async.commit_group;"); }
__device__ __forceinline__ void cp_wait1()  { asm volatile("cp.async.wait_group 1;"); }

// ---------------- tensor-core GEMM (fp16 + ldmatrix + cp.async double buffer) ----------------
template <int OUTD>
__global__ void __launch_bounds__(256, 3) mma_gemm(const float* __restrict__ W) {
    constexpr int NF = OUTD / 32;
    constexpr int P  = 68;
    extern __shared__ uint32_t smw[];
    uint32_t* Wh = smw;                    // [OUTD][P]
    uint32_t* A0 = Wh + OUTD * P;          // [64][P]
    uint32_t* A1 = A0 + 64 * P;

    const int tid  = threadIdx.x;
    const int lane = tid & 31;
    const int warp = tid >> 5;
    const int mw   = warp & 1;
    const int nw   = warp >> 1;
    const int g    = lane >> 2;
    const int tg   = lane & 3;

    for (int i = tid; i < 64 * OUTD; i += 256) {
        const int kp = i / OUTD, n = i - kp * OUTD;
        const float w0 = W[(size_t)(kp * 2)     * OUTD + n];
        const float w1 = W[(size_t)(kp * 2 + 1) * OUTD + n];
        __half2 h = __floats2half2_rn(w0, w1);
        Wh[n * P + kp] = *reinterpret_cast<uint32_t*>(&h);
    }

    const uint32_t aB0 = (uint32_t)__cvta_generic_to_shared(A0);
    const uint32_t aB1 = (uint32_t)__cvta_generic_to_shared(A1);
    const uint32_t wBase = (uint32_t)__cvta_generic_to_shared(Wh);
    const int sel = lane >> 3;
    const int li  = lane & 7;
    uint32_t aOff[2];
#pragma unroll
    for (int mf = 0; mf < 2; mf++) {
        const int row = mw * 32 + mf * 16 + (sel & 1) * 8 + li;
        aOff[mf] = (uint32_t)((row * P + (sel >> 1) * 4) * 4);
    }
    uint32_t bAddr[NF];
#pragma unroll
    for (int nf = 0; nf < NF; nf++) {
        const int n = nw * (NF * 8) + nf * 8 + li;
        bAddr[nf] = wBase + (uint32_t)((n * P + (sel & 1) * 4) * 4);
    }

    auto prefetch = [&](int tile, uint32_t bufBase) {
#pragma unroll
        for (int j = 0; j < 4; j++) {
            const int id = tid + j * 256;
            const int r = id >> 4, c16 = id & 15;
            int row = tile * 64 + r;
            if (row >= NN) row = NN - 1;   // clamp; rows>=NN never stored
            cp16(bufBase + (uint32_t)((r * P + c16 * 4) * 4),
                 g_H + (size_t)row * 128 + c16 * 8);
        }
    };

    const int ntiles = (NN + 63) / 64;
    int t = blockIdx.x;
    if (t < ntiles) prefetch(t, aB0);
    cp_commit();
    int parity = 0;

    for (; t < ntiles; t += gridDim.x) {
        const int tn = t + gridDim.x;
        if (tn < ntiles) prefetch(tn, parity ? aB0 : aB1);
        cp_commit();
        cp_wait1();
        __syncthreads();
        const uint32_t aBase = parity ? aB1 : aB0;

        float acc[2][NF][4];
#pragma unroll
        for (int mf = 0; mf < 2; mf++)
#pragma unroll
            for (int nf = 0; nf < NF; nf++)
#pragma unroll
                for (int j = 0; j < 4; j++) acc[mf][nf][j] = 0.f;

#pragma unroll
        for (int ks = 0; ks < 8; ks++) {
            uint32_t a[2][4];
            ldsm_x4(a[0], aBase + aOff[0] + ks * 32);
            ldsm_x4(a[1], aBase + aOff[1] + ks * 32);
            uint32_t b[NF][2];
#pragma unroll
            for (int nf = 0; nf < NF; nf++)
                ldsm_x2(b[nf][0], b[nf][1], bAddr[nf] + ks * 32);
#pragma unroll
            for (int nf = 0; nf < NF; nf++)
#pragma unroll
                for (int mf = 0; mf < 2; mf++)
                    mma_f16(acc[mf][nf], a[mf], b[nf][0], b[nf][1]);
        }

        const int rowbase = t * 64;
#pragma unroll
        for (int mf = 0; mf < 2; mf++) {
            const int r0 = rowbase + mw * 32 + mf * 16 + g;
#pragma unroll
            for (int nf = 0; nf < NF; nf++) {
                const int col = nw * (NF * 8) + nf * 8 + tg * 2;
                if (r0 < NN) {
                    __half2 h = __floats2half2_rn(acc[mf][nf][0], acc[mf][nf][1]);
                    *reinterpret_cast<__half2*>(&g_G[(size_t)r0 * OUTD + col]) = h;
                }
                if (r0 + 8 < NN) {
                    __half2 h = __floats2half2_rn(acc[mf][nf][2], acc[mf][nf][3]);
                    *reinterpret_cast<__half2*>(&g_G[(size_t)(r0 + 8) * OUTD + col]) = h;
                }
            }
        }
        __syncthreads();
        parity ^= 1;
    }
}

// ---------------- CSR gather aggregation: half-warp per node ----------------
// Full unpredicated batches of 8 + one predicated tail batch.
template <int WIDTH, bool FINAL>
__global__ void __launch_bounds__(256) agg_kernel(const float* __restrict__ bias,
                                                  float* __restrict__ outp) {
    const int l   = threadIdx.x & 15;
    const int ghw = (blockIdx.x * blockDim.x + threadIdx.x) >> 4;
    const int nhw = (gridDim.x * blockDim.x) >> 4;

    for (int n = ghw; n < NN; n += nhw) {
        const int2 meta = __ldg(&g_meta[n]);
        const int beg = meta.x;
        const int end = meta.x + meta.y;

        if (WIDTH == 128) {
            float accA[8] = {0,0,0,0,0,0,0,0};
            float accB[8] = {0,0,0,0,0,0,0,0};
            int e = beg;
            for (; e + 8 <= end; e += 8) {
                uint4 raw[8];
#pragma unroll
                for (int m = 0; m < 8; m++) {
                    const int s = __ldg(&g_csr_src[e + m]);
                    raw[m] = reinterpret_cast<const uint4*>(g_G + (size_t)s * 128)[l];
                }
#pragma unroll
                for (int m = 0; m < 8; m++) {
                    float* acc = (m & 1) ? accB : accA;
                    const float2 p0 = __half22float2(*reinterpret_cast<const __half2*>(&raw[m].x));
                    const float2 p1 = __half22float2(*reinterpret_cast<const __half2*>(&raw[m].y));
                    const float2 p2 = __half22float2(*reinterpret_cast<const __half2*>(&raw[m].z));
                    const float2 p3 = __half22float2(*reinterpret_cast<const __half2*>(&raw[m].w));
                    acc[0] += p0.x; acc[1] += p0.y; acc[2] += p1.x; acc[3] += p1.y;
                    acc[4] += p2.x; acc[5] += p2.y; acc[6] += p3.x; acc[7] += p3.y;
                }
            }
            if (e < end) {
                uint4 raw[8];
#pragma unroll
                for (int m = 0; m < 8; m++) {
                    const int ee = e + m;
                    const bool valid = ee < end;
                    const int s = __ldg(&g_csr_src[valid ? ee : beg]);
                    uint4 r = reinterpret_cast<const uint4*>(g_G + (size_t)s * 128)[l];
                    raw[m].x = valid ? r.x : 0u;
                    raw[m].y = valid ? r.y : 0u;
                    raw[m].z = valid ? r.z : 0u;
                    raw[m].w = valid ? r.w : 0u;
                }
#pragma unroll
                for (int m = 0; m < 8; m++) {
                    float* acc = (m & 1) ? accB : accA;
                    const float2 p0 = __half22float2(*reinterpret_cast<const __half2*>(&raw[m].x));
                    const float2 p1 = __half22float2(*reinterpret_cast<const __half2*>(&raw[m].y));
                    const float2 p2 = __half22float2(*reinterpret_cast<const __half2*>(&raw[m].z));
                    const float2 p3 = __half22float2(*reinterpret_cast<const __half2*>(&raw[m].w));
                    acc[0] += p0.x; acc[1] += p0.y; acc[2] += p1.x; acc[3] += p1.y;
                    acc[4] += p2.x; acc[5] += p2.y; acc[6] += p3.x; acc[7] += p3.y;
                }
            }
            const float ni = g_norm_in[n];
            const float no = g_norm_out[n];
            const float4 bb0 = reinterpret_cast<const float4*>(bias)[l * 2];
            const float4 bb1 = reinterpret_cast<const float4*>(bias)[l * 2 + 1];
            float r0 = fmaxf(fmaf(accA[0] + accB[0], ni, bb0.x), 0.f) * no;
            float r1 = fmaxf(fmaf(accA[1] + accB[1], ni, bb0.y), 0.f) * no;
            float r2 = fmaxf(fmaf(accA[2] + accB[2], ni, bb0.z), 0.f) * no;
            float r3 = fmaxf(fmaf(accA[3] + accB[3], ni, bb0.w), 0.f) * no;
            float r4 = fmaxf(fmaf(accA[4] + accB[4], ni, bb1.x), 0.f) * no;
            float r5 = fmaxf(fmaf(accA[5] + accB[5], ni, bb1.y), 0.f) * no;
            float r6 = fmaxf(fmaf(accA[6] + accB[6], ni, bb1.z), 0.f) * no;
            float r7 = fmaxf(fmaf(accA[7] + accB[7], ni, bb1.w), 0.f) * no;
            __half2 h0 = __floats2half2_rn(r0, r1);
            __half2 h1 = __floats2half2_rn(r2, r3);
            __half2 h2 = __floats2half2_rn(r4, r5);
            __half2 h3 = __floats2half2_rn(r6, r7);
            uint4 o;
            o.x = *reinterpret_cast<uint32_t*>(&h0);
            o.y = *reinterpret_cast<uint32_t*>(&h1);
            o.z = *reinterpret_cast<uint32_t*>(&h2);
            o.w = *reinterpret_cast<uint32_t*>(&h3);
            reinterpret_cast<uint4*>(g_H + (size_t)n * 128)[l] = o;
        } else {
            float accA[4] = {0,0,0,0};
            float accB[4] = {0,0,0,0};
            int e = beg;
            for (; e + 8 <= end; e += 8) {
                uint2 raw[8];
#pragma unroll
                for (int m = 0; m < 8; m++) {
                    const int s = __ldg(&g_csr_src[e + m]);
                    raw[m] = reinterpret_cast<const uint2*>(g_G + (size_t)s * 64)[l];
                }
#pragma unroll
                for (int m = 0; m < 8; m++) {
                    float* acc = (m & 1) ? accB : accA;
                    const float2 p0 = __half22float2(*reinterpret_cast<const __half2*>(&raw[m].x));
                    const float2 p1 = __half22float2(*reinterpret_cast<const __half2*>(&raw[m].y));
                    acc[0] += p0.x; acc[1] += p0.y; acc[2] += p1.x; acc[3] += p1.y;
                }
            }
            if (e < end) {
                uint2 raw[8];
#pragma unroll
                for (int m = 0; m < 8; m++) {
                    const int ee = e + m;
                    const bool valid = ee < end;
                    const int s = __ldg(&g_csr_src[valid ? ee : beg]);
                    uint2 r = reinterpret_cast<const uint2*>(g_G + (size_t)s * 64)[l];
                    raw[m].x = valid ? r.x : 0u;
                    raw[m].y = valid ? r.y : 0u;
                }
#pragma unroll
                for (int m = 0; m < 8; m++) {
                    float* acc = (m & 1) ? accB : accA;
                    const float2 p0 = __half22float2(*reinterpret_cast<const __half2*>(&raw[m].x));
                    const float2 p1 = __half22float2(*reinterpret_cast<const __half2*>(&raw[m].y));
                    acc[0] += p0.x; acc[1] += p0.y; acc[2] += p1.x; acc[3] += p1.y;
                }
            }
            const float ni = g_norm_in[n];
            const float4 bb = reinterpret_cast<const float4*>(bias)[l];
            float4 o;
            o.x = fmaf(accA[0] + accB[0], ni, bb.x);
            o.y = fmaf(accA[1] + accB[1], ni, bb.y);
            o.z = fmaf(accA[2] + accB[2], ni, bb.z);
            o.w = fmaf(accA[3] + accB[3], ni, bb.w);
            reinterpret_cast<float4*>(outp + (size_t)n * 64)[l] = o;
        }
    }
}

// ---------------- launch ----------------
extern "C" void kernel_launch(void* const* d_in, const int* in_sizes, int n_in,
                              void* d_out, int out_size) {
    const float* feat = (const float*)d_in[0];
    const int*   src  = (const int*)d_in[1];
    const int*   dst  = (const int*)d_in[2];
    const float* W0   = (const float*)d_in[3];
    const float* b0   = (const float*)d_in[4];
    const float* W1   = (const float*)d_in[5];
    const float* b1   = (const float*)d_in[6];
    const float* W2   = (const float*)d_in[7];
    const float* b2   = (const float*)d_in[8];
    float* out = (float*)d_out;

    // persistent side stream + events (host-side resources, created once)
    static cudaStream_t s2 = nullptr;
    static cudaEvent_t evFork = nullptr, evJoin = nullptr;
    if (s2 == nullptr) {
        cudaStreamCreateWithFlags(&s2, cudaStreamNonBlocking);
        cudaEventCreateWithFlags(&evFork, cudaEventDisableTiming);
        cudaEventCreateWithFlags(&evJoin, cudaEventDisableTiming);
    }

    const int SM128 = (128 * 68 + 2 * 64 * 68) * 4;  // 69632 B
    const int SM64  = (64 * 68 + 2 * 64 * 68) * 4;   // 52224 B
    cudaFuncSetAttribute(mma_gemm<128>, cudaFuncAttributeMaxDynamicSharedMemorySize, SM128);
    cudaFuncSetAttribute(mma_gemm<64>,  cudaFuncAttributeMaxDynamicSharedMemorySize, SM64);

    const int T = 256;
    const int GGRID = 444;   // 3 CTAs/SM
    const int AGRID = 1184;

    // main stream: histogram (both branches depend on it)
    zero_kernel<<<(NN + T - 1) / T, T>>>();
    hist_kernel<<<(NE + T - 1) / T, T>>>(src, dst);

    // fork: CSR offsets/placement on s2, concurrent with norm_conv + GEMM0
    cudaEventRecord(evFork, 0);
    cudaStreamWaitEvent(s2, evFork, 0);
    scan1_kernel<<<NBLK_SCAN, 256, 0, s2>>>();
    scan2_kernel<<<1, 256, 0, s2>>>();
    scan3_kernel<<<(NN + T - 1) / T, T, 0, s2>>>();
    place_kernel<<<(NE + T - 1) / T, T, 0, s2>>>(src, dst);
    cudaEventRecord(evJoin, s2);

    norm_conv_kernel<<<(NN * 32 + T - 1) / T, T>>>(feat);
    mma_gemm<128><<<GGRID, T, SM128>>>(W0);

    // join: agg needs both GEMM0 (g_G) and CSR (meta/csr_src)
    cudaStreamWaitEvent(0, evJoin, 0);

    agg_kernel<128, false><<<AGRID, T>>>(b0, nullptr);

    mma_gemm<128><<<GGRID, T, SM128>>>(W1);
    agg_kernel<128, false><<<AGRID, T>>>(b1, nullptr);

    mma_gemm<64><<<GGRID, T, SM64>>>(W2);
    agg_kernel<64, true><<<AGRID, T>>>(b2, out);
}

// round 12
// speedup vs baseline: 1.0188x; 1.0188x over previous
#include <cuda_runtime.h>
#include <cuda_fp16.h>
#include <cstdint>
#include <cstddef>

#define NN 170000
#define NE 1200000
#define NBLK_SCAN 167        // ceil(NN / 1024)

// ---------------- device scratch (allocation-free) ----------------
__device__ __half g_G[(size_t)NN * 128];  // GEMM output (fp16)
__device__ __half g_H[(size_t)NN * 128];  // GEMM A source (fp16)
__device__ int    g_deg_out[NN];
__device__ int    g_cnt[NN];
__device__ int    g_off[NN];
__device__ int2   g_meta[NN];             // {offset, count}
__device__ int    g_fill[NN];
__device__ int    g_bsum[NBLK_SCAN];
__device__ float  g_norm_out[NN];
__device__ float  g_norm_in[NN];
__device__ int    g_csr_src[NE];

// ---------------- CSR build ----------------
__global__ void zero_kernel() {
    int i = blockIdx.x * blockDim.x + threadIdx.x;
    if (i < NN) { g_deg_out[i] = 0; g_cnt[i] = 0; g_fill[i] = 0; }
}

__global__ void hist_kernel(const int* __restrict__ src, const int* __restrict__ dst) {
    int e = blockIdx.x * blockDim.x + threadIdx.x;
    if (e < NE) {
        atomicAdd(&g_deg_out[src[e]], 1);
        atomicAdd(&g_cnt[dst[e]], 1);
    }
}

// norms + feat*norm_out -> g_H (fp16), fused
__global__ void norm_conv_kernel(const float* __restrict__ X) {
    int i = blockIdx.x * blockDim.x + threadIdx.x;   // over NN*32 float4s
    if (i >= NN * 32) return;
    const int row = i >> 5;
    int din  = g_cnt[row];     if (din  < 1) din  = 1;
    int dout = g_deg_out[row]; if (dout < 1) dout = 1;
    const float no = rsqrtf((float)dout);
    if ((i & 31) == 0) {
        g_norm_in[row]  = rsqrtf((float)din);
        g_norm_out[row] = no;
    }
    float4 v = reinterpret_cast<const float4*>(X)[i];
    __half2 h0 = __floats2half2_rn(v.x * no, v.y * no);
    __half2 h1 = __floats2half2_rn(v.z * no, v.w * no);
    uint2 o;
    o.x = *reinterpret_cast<uint32_t*>(&h0);
    o.y = *reinterpret_cast<uint32_t*>(&h1);
    reinterpret_cast<uint2*>(g_H)[i] = o;
}

__global__ void scan1_kernel() {
    __shared__ int sh[256];
    const int t = threadIdx.x;
    const int base = blockIdx.x * 1024 + t * 4;
    int c0 = 0, c1 = 0, c2 = 0, c3 = 0;
    if (base + 3 < NN) {
        int4 v = *reinterpret_cast<const int4*>(&g_cnt[base]);
        c0 = v.x; c1 = v.y; c2 = v.z; c3 = v.w;
    } else {
        if (base     < NN) c0 = g_cnt[base];
        if (base + 1 < NN) c1 = g_cnt[base + 1];
        if (base + 2 < NN) c2 = g_cnt[base + 2];
        if (base + 3 < NN) c3 = g_cnt[base + 3];
    }
    const int mysum = c0 + c1 + c2 + c3;
    sh[t] = mysum;
    __syncthreads();
    for (int off = 1; off < 256; off <<= 1) {
        int v = (t >= off) ? sh[t - off] : 0;
        __syncthreads();
        sh[t] += v;
        __syncthreads();
    }
    const int excl = sh[t] - mysum;
    if (t == 255) g_bsum[blockIdx.x] = sh[255];
    if (base     < NN) g_off[base]     = excl;
    if (base + 1 < NN) g_off[base + 1] = excl + c0;
    if (base + 2 < NN) g_off[base + 2] = excl + c0 + c1;
    if (base + 3 < NN) g_off[base + 3] = excl + c0 + c1 + c2;
}

__global__ void scan2_kernel() {
    __shared__ int sh[256];
    const int t = threadIdx.x;
    int v = (t < NBLK_SCAN) ? g_bsum[t] : 0;
    sh[t] = v;
    __syncthreads();
    for (int off = 1; off < 256; off <<= 1) {
        int u = (t >= off) ? sh[t - off] : 0;
        __syncthreads();
        sh[t] += u;
        __syncthreads();
    }
    if (t < NBLK_SCAN) g_bsum[t] = sh[t] - v;
}

__global__ void scan3_kernel() {
    int i = blockIdx.x * blockDim.x + threadIdx.x;
    if (i < NN) {
        const int off = g_off[i] + g_bsum[i >> 10];
        g_off[i] = off;
        g_meta[i] = make_int2(off, g_cnt[i]);
    }
}

__global__ void place_kernel(const int* __restrict__ src, const int* __restrict__ dst) {
    int e = blockIdx.x * blockDim.x + threadIdx.x;
    if (e < NE) {
        const int d = dst[e];
        const int pos = g_off[d] + atomicAdd(&g_fill[d], 1);
        g_csr_src[pos] = src[e];
    }
}

// ---------------- mma / ldmatrix / cp.async helpers ----------------
__device__ __forceinline__ void mma_f16(float* c, const uint32_t* a, uint32_t b0, uint32_t b1) {
    asm volatile(
        "mma.sync.aligned.m16n8k16.row.col.f32.f16.f16.f32 "
        "{%0,%1,%2,%3}, {%4,%5,%6,%7}, {%8,%9}, {%0,%1,%2,%3};"
        : "+f"(c[0]), "+f"(c[1]), "+f"(c[2]), "+f"(c[3])
        : "r"(a[0]), "r"(a[1]), "r"(a[2]), "r"(a[3]), "r"(b0), "r"(b1));
}

__device__ __forceinline__ void ldsm_x4(uint32_t* r, uint32_t addr) {
    asm volatile("ldmatrix.sync.aligned.m8n8.x4.shared.b16 {%0,%1,%2,%3}, [%4];"
                 : "=r"(r[0]), "=r"(r[1]), "=r"(r[2]), "=r"(r[3]) : "r"(addr));
}

__device__ __forceinline__ void ldsm_x2(uint32_t& r0, uint32_t& r1, uint32_t addr) {
    asm volatile("ldmatrix.sync.aligned.m8n8.x2.shared.b16 {%0,%1}, [%2];"
                 : "=r"(r0), "=r"(r1) : "r"(addr));
}

__device__ __forceinline__ void cp16(uint32_t dst, const void* src) {
    asm volatile("cp.async.cg.shared.global [%0], [%1], 16;" :: "r"(dst), "l"(src));
}
__device__ __forceinline__ void cp_commit() { asm volatile("cp.async.commit_group;"); }
__device__ __forceinline__ void cp_wait1()  { asm volatile("cp.async.wait_group 1;"); }

// ---------------- tensor-core GEMM (fp16 + ldmatrix + cp.async double buffer) ----------------
template <int OUTD>
__global__ void __launch_bounds__(256, 3) mma_gemm(const float* __restrict__ W) {
    constexpr int NF = OUTD / 32;
    constexpr int P  = 68;
    extern __shared__ uint32_t smw[];
    uint32_t* Wh = smw;                    // [OUTD][P]
    uint32_t* A0 = Wh + OUTD * P;          // [64][P]
    uint32_t* A1 = A0 + 64 * P;

    const int tid  = threadIdx.x;
    const int lane = tid & 31;
    const int warp = tid >> 5;
    const int mw   = warp & 1;
    const int nw   = warp >> 1;
    const int g    = lane >> 2;
    const int tg   = lane & 3;

    for (int i = tid; i < 64 * OUTD; i += 256) {
        const int kp = i / OUTD, n = i - kp * OUTD;
        const float w0 = W[(size_t)(kp * 2)     * OUTD + n];
        const float w1 = W[(size_t)(kp * 2 + 1) * OUTD + n];
        __half2 h = __floats2half2_rn(w0, w1);
        Wh[n * P + kp] = *reinterpret_cast<uint32_t*>(&h);
    }

    const uint32_t aB0 = (uint32_t)__cvta_generic_to_shared(A0);
    const uint32_t aB1 = (uint32_t)__cvta_generic_to_shared(A1);
    const uint32_t wBase = (uint32_t)__cvta_generic_to_shared(Wh);
    const int sel = lane >> 3;
    const int li  = lane & 7;
    uint32_t aOff[2];
#pragma unroll
    for (int mf = 0; mf < 2; mf++) {
        const int row = mw * 32 + mf * 16 + (sel & 1) * 8 + li;
        aOff[mf] = (uint32_t)((row * P + (sel >> 1) * 4) * 4);
    }
    uint32_t bAddr[NF];
#pragma unroll
    for (int nf = 0; nf < NF; nf++) {
        const int n = nw * (NF * 8) + nf * 8 + li;
        bAddr[nf] = wBase + (uint32_t)((n * P + (sel & 1) * 4) * 4);
    }

    auto prefetch = [&](int tile, uint32_t bufBase) {
#pragma unroll
        for (int j = 0; j < 4; j++) {
            const int id = tid + j * 256;
            const int r = id >> 4, c16 = id & 15;
            int row = tile * 64 + r;
            if (row >= NN) row = NN - 1;   // clamp; rows>=NN never stored
            cp16(bufBase + (uint32_t)((r * P + c16 * 4) * 4),
                 g_H + (size_t)row * 128 + c16 * 8);
        }
    };

    const int ntiles = (NN + 63) / 64;
    int t = blockIdx.x;
    if (t < ntiles) prefetch(t, aB0);
    cp_commit();
    int parity = 0;

    for (; t < ntiles; t += gridDim.x) {
        const int tn = t + gridDim.x;
        if (tn < ntiles) prefetch(tn, parity ? aB0 : aB1);
        cp_commit();
        cp_wait1();
        __syncthreads();
        const uint32_t aBase = parity ? aB1 : aB0;

        float acc[2][NF][4];
#pragma unroll
        for (int mf = 0; mf < 2; mf++)
#pragma unroll
            for (int nf = 0; nf < NF; nf++)
#pragma unroll
                for (int j = 0; j < 4; j++) acc[mf][nf][j] = 0.f;

#pragma unroll
        for (int ks = 0; ks < 8; ks++) {
            uint32_t a[2][4];
            ldsm_x4(a[0], aBase + aOff[0] + ks * 32);
            ldsm_x4(a[1], aBase + aOff[1] + ks * 32);
            uint32_t b[NF][2];
#pragma unroll
            for (int nf = 0; nf < NF; nf++)
                ldsm_x2(b[nf][0], b[nf][1], bAddr[nf] + ks * 32);
#pragma unroll
            for (int nf = 0; nf < NF; nf++)
#pragma unroll
                for (int mf = 0; mf < 2; mf++)
                    mma_f16(acc[mf][nf], a[mf], b[nf][0], b[nf][1]);
        }

        const int rowbase = t * 64;
#pragma unroll
        for (int mf = 0; mf < 2; mf++) {
            const int r0 = rowbase + mw * 32 + mf * 16 + g;
#pragma unroll
            for (int nf = 0; nf < NF; nf++) {
                const int col = nw * (NF * 8) + nf * 8 + tg * 2;
                if (r0 < NN) {
                    __half2 h = __floats2half2_rn(acc[mf][nf][0], acc[mf][nf][1]);
                    *reinterpret_cast<__half2*>(&g_G[(size_t)r0 * OUTD + col]) = h;
                }
                if (r0 + 8 < NN) {
                    __half2 h = __floats2half2_rn(acc[mf][nf][2], acc[mf][nf][3]);
                    *reinterpret_cast<__half2*>(&g_G[(size_t)(r0 + 8) * OUTD + col]) = h;
                }
            }
        }
        __syncthreads();
        parity ^= 1;
    }
}

// ---------------- CSR gather aggregation: half-warp per node ----------------
// Full unpredicated batches of 8 + one predicated tail batch.
template <int WIDTH, bool FINAL>
__global__ void __launch_bounds__(256) agg_kernel(const float* __restrict__ bias,
                                                  float* __restrict__ outp) {
    const int l   = threadIdx.x & 15;
    const int ghw = (blockIdx.x * blockDim.x + threadIdx.x) >> 4;
    const int nhw = (gridDim.x * blockDim.x) >> 4;

    for (int n = ghw; n < NN; n += nhw) {
        const int2 meta = __ldg(&g_meta[n]);
        const int beg = meta.x;
        const int end = meta.x + meta.y;

        if (WIDTH == 128) {
            float accA[8] = {0,0,0,0,0,0,0,0};
            float accB[8] = {0,0,0,0,0,0,0,0};
            int e = beg;
            for (; e + 8 <= end; e += 8) {
                uint4 raw[8];
#pragma unroll
                for (int m = 0; m < 8; m++) {
                    const int s = __ldg(&g_csr_src[e + m]);
                    raw[m] = reinterpret_cast<const uint4*>(g_G + (size_t)s * 128)[l];
                }
#pragma unroll
                for (int m = 0; m < 8; m++) {
                    float* acc = (m & 1) ? accB : accA;
                    const float2 p0 = __half22float2(*reinterpret_cast<const __half2*>(&raw[m].x));
                    const float2 p1 = __half22float2(*reinterpret_cast<const __half2*>(&raw[m].y));
                    const float2 p2 = __half22float2(*reinterpret_cast<const __half2*>(&raw[m].z));
                    const float2 p3 = __half22float2(*reinterpret_cast<const __half2*>(&raw[m].w));
                    acc[0] += p0.x; acc[1] += p0.y; acc[2] += p1.x; acc[3] += p1.y;
                    acc[4] += p2.x; acc[5] += p2.y; acc[6] += p3.x; acc[7] += p3.y;
                }
            }
            if (e < end) {
                uint4 raw[8];
#pragma unroll
                for (int m = 0; m < 8; m++) {
                    const int ee = e + m;
                    const bool valid = ee < end;
                    const int s = __ldg(&g_csr_src[valid ? ee : beg]);
                    uint4 r = reinterpret_cast<const uint4*>(g_G + (size_t)s * 128)[l];
                    raw[m].x = valid ? r.x : 0u;
                    raw[m].y = valid ? r.y : 0u;
                    raw[m].z = valid ? r.z : 0u;
                    raw[m].w = valid ? r.w : 0u;
                }
#pragma unroll
                for (int m = 0; m < 8; m++) {
                    float* acc = (m & 1) ? accB : accA;
                    const float2 p0 = __half22float2(*reinterpret_cast<const __half2*>(&raw[m].x));
                    const float2 p1 = __half22float2(*reinterpret_cast<const __half2*>(&raw[m].y));
                    const float2 p2 = __half22float2(*reinterpret_cast<const __half2*>(&raw[m].z));
                    const float2 p3 = __half22float2(*reinterpret_cast<const __half2*>(&raw[m].w));
                    acc[0] += p0.x; acc[1] += p0.y; acc[2] += p1.x; acc[3] += p1.y;
                    acc[4] += p2.x; acc[5] += p2.y; acc[6] += p3.x; acc[7] += p3.y;
                }
            }
            const float ni = g_norm_in[n];
            const float no = g_norm_out[n];
            const float4 bb0 = reinterpret_cast<const float4*>(bias)[l * 2];
            const float4 bb1 = reinterpret_cast<const float4*>(bias)[l * 2 + 1];
            float r0 = fmaxf(fmaf(accA[0] + accB[0], ni, bb0.x), 0.f) * no;
            float r1 = fmaxf(fmaf(accA[1] + accB[1], ni, bb0.y), 0.f) * no;
            float r2 = fmaxf(fmaf(accA[2] + accB[2], ni, bb0.z), 0.f) * no;
            float r3 = fmaxf(fmaf(accA[3] + accB[3], ni, bb0.w), 0.f) * no;
            float r4 = fmaxf(fmaf(accA[4] + accB[4], ni, bb1.x), 0.f) * no;
            float r5 = fmaxf(fmaf(accA[5] + accB[5], ni, bb1.y), 0.f) * no;
            float r6 = fmaxf(fmaf(accA[6] + accB[6], ni, bb1.z), 0.f) * no;
            float r7 = fmaxf(fmaf(accA[7] + accB[7], ni, bb1.w), 0.f) * no;
            __half2 h0 = __floats2half2_rn(r0, r1);
            __half2 h1 = __floats2half2_rn(r2, r3);
            __half2 h2 = __floats2half2_rn(r4, r5);
            __half2 h3 = __floats2half2_rn(r6, r7);
            uint4 o;
            o.x = *reinterpret_cast<uint32_t*>(&h0);
            o.y = *reinterpret_cast<uint32_t*>(&h1);
            o.z = *reinterpret_cast<uint32_t*>(&h2);
            o.w = *reinterpret_cast<uint32_t*>(&h3);
            reinterpret_cast<uint4*>(g_H + (size_t)n * 128)[l] = o;
        } else {
            float accA[4] = {0,0,0,0};
            float accB[4] = {0,0,0,0};
            int e = beg;
            for (; e + 8 <= end; e += 8) {
                uint2 raw[8];
#pragma unroll
                for (int m = 0; m < 8; m++) {
                    const int s = __ldg(&g_csr_src[e + m]);
                    raw[m] = reinterpret_cast<const uint2*>(g_G + (size_t)s * 64)[l];
                }
#pragma unroll
                for (int m = 0; m < 8; m++) {
                    float* acc = (m & 1) ? accB : accA;
                    const float2 p0 = __half22float2(*reinterpret_cast<const __half2*>(&raw[m].x));
                    const float2 p1 = __half22float2(*reinterpret_cast<const __half2*>(&raw[m].y));
                    acc[0] += p0.x; acc[1] += p0.y; acc[2] += p1.x; acc[3] += p1.y;
                }
            }
            if (e < end) {
                uint2 raw[8];
#pragma unroll
                for (int m = 0; m < 8; m++) {
                    const int ee = e + m;
                    const bool valid = ee < end;
                    const int s = __ldg(&g_csr_src[valid ? ee : beg]);
                    uint2 r = reinterpret_cast<const uint2*>(g_G + (size_t)s * 64)[l];
                    raw[m].x = valid ? r.x : 0u;
                    raw[m].y = valid ? r.y : 0u;
                }
#pragma unroll
                for (int m = 0; m < 8; m++) {
                    float* acc = (m & 1) ? accB : accA;
                    const float2 p0 = __half22float2(*reinterpret_cast<const __half2*>(&raw[m].x));
                    const float2 p1 = __half22float2(*reinterpret_cast<const __half2*>(&raw[m].y));
                    acc[0] += p0.x; acc[1] += p0.y; acc[2] += p1.x; acc[3] += p1.y;
                }
            }
            const float ni = g_norm_in[n];
            const float4 bb = reinterpret_cast<const float4*>(bias)[l];
            float4 o;
            o.x = fmaf(accA[0] + accB[0], ni, bb.x);
            o.y = fmaf(accA[1] + accB[1], ni, bb.y);
            o.z = fmaf(accA[2] + accB[2], ni, bb.z);
            o.w = fmaf(accA[3] + accB[3], ni, bb.w);
            reinterpret_cast<float4*>(outp + (size_t)n * 64)[l] = o;
        }
    }
}

// ---------------- launch ----------------
extern "C" void kernel_launch(void* const* d_in, const int* in_sizes, int n_in,
                              void* d_out, int out_size) {
    const float* feat = (const float*)d_in[0];
    const int*   src  = (const int*)d_in[1];
    const int*   dst  = (const int*)d_in[2];
    const float* W0   = (const float*)d_in[3];
    const float* b0   = (const float*)d_in[4];
    const float* W1   = (const float*)d_in[5];
    const float* b1   = (const float*)d_in[6];
    const float* W2   = (const float*)d_in[7];
    const float* b2   = (const float*)d_in[8];
    float* out = (float*)d_out;

    const int SM128 = (128 * 68 + 2 * 64 * 68) * 4;  // 69632 B
    const int SM64  = (64 * 68 + 2 * 64 * 68) * 4;   // 52224 B
    cudaFuncSetAttribute(mma_gemm<128>, cudaFuncAttributeMaxDynamicSharedMemorySize, SM128);
    cudaFuncSetAttribute(mma_gemm<64>,  cudaFuncAttributeMaxDynamicSharedMemorySize, SM64);

    const int T = 256;
    const int GGRID = 444;   // 3 CTAs/SM
    const int AGRID = 1184;

    // 1-3: histogram, norms + feat conversion
    zero_kernel<<<(NN + T - 1) / T, T>>>();
    hist_kernel<<<(NE + T - 1) / T, T>>>(src, dst);
    norm_conv_kernel<<<(NN * 32 + T - 1) / T, T>>>(feat);
    // 4: layer-0 GEMM (profiled slot)
    mma_gemm<128><<<GGRID, T, SM128>>>(W0);
    // 5-8: CSR build
    scan1_kernel<<<NBLK_SCAN, 256>>>();
    scan2_kernel<<<1, 256>>>();
    scan3_kernel<<<(NN + T - 1) / T, T>>>();
    place_kernel<<<(NE + T - 1) / T, T>>>(src, dst);

    // layer 0 aggregation -> g_H
    agg_kernel<128, false><<<AGRID, T>>>(b0, nullptr);

    // layer 1
    mma_gemm<128><<<GGRID, T, SM128>>>(W1);
    agg_kernel<128, false><<<AGRID, T>>>(b1, nullptr);

    // layer 2 (64-wide)
    mma_gemm<64><<<GGRID, T, SM64>>>(W2);
    agg_kernel<64, true><<<AGRID, T>>>(b2, out);
}

// round 13
// speedup vs baseline: 1.0700x; 1.0503x over previous
#include <cuda_runtime.h>
#include <cuda_fp16.h>
#include <cstdint>
#include <cstddef>

#define NN 170000
#define NE 1200000
#define NBLK_SCAN 167        // ceil(NN / 1024)

// ---------------- device scratch (allocation-free) ----------------
__device__ __half g_G[(size_t)NN * 128];  // GEMM output (fp16)
__device__ __half g_H[(size_t)NN * 128];  // GEMM A source (fp16)
__device__ int    g_deg_out[NN];
__device__ int    g_cnt[NN];
__device__ int    g_off[NN];
__device__ int2   g_meta[NN];             // {offset, count}
__device__ int    g_fill[NN];
__device__ int    g_bsum[NBLK_SCAN];
__device__ float  g_norm_out[NN];
__device__ float  g_norm_in[NN];
__device__ int    g_csr_src[NE];

// ---------------- CSR build ----------------
__global__ void zero_kernel() {
    int i = blockIdx.x * blockDim.x + threadIdx.x;
    if (i < NN) { g_deg_out[i] = 0; g_cnt[i] = 0; g_fill[i] = 0; }
}

__global__ void hist_kernel(const int* __restrict__ src, const int* __restrict__ dst) {
    int e = blockIdx.x * blockDim.x + threadIdx.x;
    if (e < NE) {
        atomicAdd(&g_deg_out[src[e]], 1);
        atomicAdd(&g_cnt[dst[e]], 1);
    }
}

__global__ void norm_kernel() {
    int i = blockIdx.x * blockDim.x + threadIdx.x;
    if (i < NN) {
        int din  = g_cnt[i];     if (din  < 1) din  = 1;
        int dout = g_deg_out[i]; if (dout < 1) dout = 1;
        g_norm_in[i]  = rsqrtf((float)din);
        g_norm_out[i] = rsqrtf((float)dout);
    }
}

__global__ void scan1_kernel() {
    __shared__ int sh[256];
    const int t = threadIdx.x;
    const int base = blockIdx.x * 1024 + t * 4;
    int c0 = 0, c1 = 0, c2 = 0, c3 = 0;
    if (base + 3 < NN) {
        int4 v = *reinterpret_cast<const int4*>(&g_cnt[base]);
        c0 = v.x; c1 = v.y; c2 = v.z; c3 = v.w;
    } else {
        if (base     < NN) c0 = g_cnt[base];
        if (base + 1 < NN) c1 = g_cnt[base + 1];
        if (base + 2 < NN) c2 = g_cnt[base + 2];
        if (base + 3 < NN) c3 = g_cnt[base + 3];
    }
    const int mysum = c0 + c1 + c2 + c3;
    sh[t] = mysum;
    __syncthreads();
    for (int off = 1; off < 256; off <<= 1) {
        int v = (t >= off) ? sh[t - off] : 0;
        __syncthreads();
        sh[t] += v;
        __syncthreads();
    }
    const int excl = sh[t] - mysum;
    if (t == 255) g_bsum[blockIdx.x] = sh[255];
    if (base     < NN) g_off[base]     = excl;
    if (base + 1 < NN) g_off[base + 1] = excl + c0;
    if (base + 2 < NN) g_off[base + 2] = excl + c0 + c1;
    if (base + 3 < NN) g_off[base + 3] = excl + c0 + c1 + c2;
}

__global__ void scan2_kernel() {
    __shared__ int sh[256];
    const int t = threadIdx.x;
    int v = (t < NBLK_SCAN) ? g_bsum[t] : 0;
    sh[t] = v;
    __syncthreads();
    for (int off = 1; off < 256; off <<= 1) {
        int u = (t >= off) ? sh[t - off] : 0;
        __syncthreads();
        sh[t] += u;
        __syncthreads();
    }
    if (t < NBLK_SCAN) g_bsum[t] = sh[t] - v;
}

__global__ void scan3_kernel() {
    int i = blockIdx.x * blockDim.x + threadIdx.x;
    if (i < NN) {
        const int off = g_off[i] + g_bsum[i >> 10];
        g_off[i] = off;
        g_meta[i] = make_int2(off, g_cnt[i]);
    }
}

__global__ void place_kernel(const int* __restrict__ src, const int* __restrict__ dst) {
    int e = blockIdx.x * blockDim.x + threadIdx.x;
    if (e < NE) {
        const int d = dst[e];
        const int pos = g_off[d] + atomicAdd(&g_fill[d], 1);
        g_csr_src[pos] = src[e];
    }
}

// ---------------- mma / ldmatrix / cp.async helpers ----------------
__device__ __forceinline__ void mma_f16(float* c, const uint32_t* a, uint32_t b0, uint32_t b1) {
    asm volatile(
        "mma.sync.aligned.m16n8k16.row.col.f32.f16.f16.f32 "
        "{%0,%1,%2,%3}, {%4,%5,%6,%7}, {%8,%9}, {%0,%1,%2,%3};"
        : "+f"(c[0]), "+f"(c[1]), "+f"(c[2]), "+f"(c[3])
        : "r"(a[0]), "r"(a[1]), "r"(a[2]), "r"(a[3]), "r"(b0), "r"(b1));
}

__device__ __forceinline__ void ldsm_x4(uint32_t* r, uint32_t addr) {
    asm volatile("ldmatrix.sync.aligned.m8n8.x4.shared.b16 {%0,%1,%2,%3}, [%4];"
                 : "=r"(r[0]), "=r"(r[1]), "=r"(r[2]), "=r"(r[3]) : "r"(addr));
}

__device__ __forceinline__ void ldsm_x2(uint32_t& r0, uint32_t& r1, uint32_t addr) {
    asm volatile("ldmatrix.sync.aligned.m8n8.x2.shared.b16 {%0,%1}, [%2];"
                 : "=r"(r0), "=r"(r1) : "r"(addr));
}

__device__ __forceinline__ void cp16(uint32_t dst, const void* src) {
    asm volatile("cp.async.cg.shared.global [%0], [%1], 16;" :: "r"(dst), "l"(src));
}
__device__ __forceinline__ void cp_commit() { asm volatile("cp.async.commit_group;"); }
__device__ __forceinline__ void cp_wait1()  { asm volatile("cp.async.wait_group 1;"); }

// ---------------- tensor-core GEMM (fp16 m16n8k16 + ldmatrix) ----------------
// SRC_H=false (layer 0): synchronous A build from fp32 X * norm_out (fused convert; no
//   standalone conversion pass). 1 A buffer.
// SRC_H=true (layers 1,2): cp.async double-buffered bit-copy from fp16 g_H. 2 A buffers.
template <int OUTD, bool SRC_H>
__global__ void __launch_bounds__(256, 3) mma_gemm(const float* __restrict__ X,
                                                   const float* __restrict__ W) {
    constexpr int NF = OUTD / 32;
    constexpr int P  = 68;
    extern __shared__ uint32_t smw[];
    uint32_t* Wh = smw;                    // [OUTD][P]
    uint32_t* A0 = Wh + OUTD * P;          // [64][P]
    uint32_t* A1 = A0 + 64 * P;            // [64][P] (pipeline path only)

    const int tid  = threadIdx.x;
    const int lane = tid & 31;
    const int warp = tid >> 5;
    const int mw   = warp & 1;
    const int nw   = warp >> 1;
    const int g    = lane >> 2;
    const int tg   = lane & 3;

    for (int i = tid; i < 64 * OUTD; i += 256) {
        const int kp = i / OUTD, n = i - kp * OUTD;
        const float w0 = W[(size_t)(kp * 2)     * OUTD + n];
        const float w1 = W[(size_t)(kp * 2 + 1) * OUTD + n];
        __half2 h = __floats2half2_rn(w0, w1);
        Wh[n * P + kp] = *reinterpret_cast<uint32_t*>(&h);
    }

    const uint32_t aB0 = (uint32_t)__cvta_generic_to_shared(A0);
    const uint32_t aB1 = (uint32_t)__cvta_generic_to_shared(A1);
    const uint32_t wBase = (uint32_t)__cvta_generic_to_shared(Wh);
    const int sel = lane >> 3;
    const int li  = lane & 7;
    uint32_t aOff[2];
#pragma unroll
    for (int mf = 0; mf < 2; mf++) {
        const int row = mw * 32 + mf * 16 + (sel & 1) * 8 + li;
        aOff[mf] = (uint32_t)((row * P + (sel >> 1) * 4) * 4);
    }
    uint32_t bAddr[NF];
#pragma unroll
    for (int nf = 0; nf < NF; nf++) {
        const int n = nw * (NF * 8) + nf * 8 + li;
        bAddr[nf] = wBase + (uint32_t)((n * P + (sel & 1) * 4) * 4);
    }

    const int ntiles = (NN + 63) / 64;

    // ---- core compute on a ready A buffer ----
    auto compute_store = [&](uint32_t aBase, int rowbase) {
        float acc[2][NF][4];
#pragma unroll
        for (int mf = 0; mf < 2; mf++)
#pragma unroll
            for (int nf = 0; nf < NF; nf++)
#pragma unroll
                for (int j = 0; j < 4; j++) acc[mf][nf][j] = 0.f;

#pragma unroll
        for (int ks = 0; ks < 8; ks++) {
            uint32_t a[2][4];
            ldsm_x4(a[0], aBase + aOff[0] + ks * 32);
            ldsm_x4(a[1], aBase + aOff[1] + ks * 32);
            uint32_t b[NF][2];
#pragma unroll
            for (int nf = 0; nf < NF; nf++)
                ldsm_x2(b[nf][0], b[nf][1], bAddr[nf] + ks * 32);
#pragma unroll
            for (int nf = 0; nf < NF; nf++)
#pragma unroll
                for (int mf = 0; mf < 2; mf++)
                    mma_f16(acc[mf][nf], a[mf], b[nf][0], b[nf][1]);
        }

#pragma unroll
        for (int mf = 0; mf < 2; mf++) {
            const int r0 = rowbase + mw * 32 + mf * 16 + g;
#pragma unroll
            for (int nf = 0; nf < NF; nf++) {
                const int col = nw * (NF * 8) + nf * 8 + tg * 2;
                if (r0 < NN) {
                    __half2 h = __floats2half2_rn(acc[mf][nf][0], acc[mf][nf][1]);
                    *reinterpret_cast<__half2*>(&g_G[(size_t)r0 * OUTD + col]) = h;
                }
                if (r0 + 8 < NN) {
                    __half2 h = __floats2half2_rn(acc[mf][nf][2], acc[mf][nf][3]);
                    *reinterpret_cast<__half2*>(&g_G[(size_t)(r0 + 8) * OUTD + col]) = h;
                }
            }
        }
    };

    if (SRC_H) {
        // pipelined path: cp.async fp16 bit-copy, double buffer
        auto prefetch = [&](int tile, uint32_t bufBase) {
#pragma unroll
            for (int j = 0; j < 4; j++) {
                const int id = tid + j * 256;
                const int r = id >> 4, c16 = id & 15;
                int row = tile * 64 + r;
                if (row >= NN) row = NN - 1;   // clamp; rows>=NN never stored
                cp16(bufBase + (uint32_t)((r * P + c16 * 4) * 4),
                     g_H + (size_t)row * 128 + c16 * 8);
            }
        };

        int t = blockIdx.x;
        if (t < ntiles) prefetch(t, aB0);
        cp_commit();
        int parity = 0;
        for (; t < ntiles; t += gridDim.x) {
            const int tn = t + gridDim.x;
            if (tn < ntiles) prefetch(tn, parity ? aB0 : aB1);
            cp_commit();
            cp_wait1();
            __syncthreads();
            compute_store(parity ? aB1 : aB0, t * 64);
            __syncthreads();
            parity ^= 1;
        }
    } else {
        // synchronous path: fp32 X * norm_out -> fp16, single buffer
        for (int t = blockIdx.x; t < ntiles; t += gridDim.x) {
            __syncthreads();
            const int rowbase = t * 64;
            for (int i = tid; i < 64 * 32; i += 256) {
                const int r = i >> 5, c4 = i & 31;
                const int row = rowbase + r;
                uint32_t w0 = 0, w1 = 0;
                if (row < NN) {
                    float4 v = reinterpret_cast<const float4*>(X + (size_t)row * 128)[c4];
                    const float no = g_norm_out[row];
                    __half2 h0 = __floats2half2_rn(v.x * no, v.y * no);
                    __half2 h1 = __floats2half2_rn(v.z * no, v.w * no);
                    w0 = *reinterpret_cast<uint32_t*>(&h0);
                    w1 = *reinterpret_cast<uint32_t*>(&h1);
                }
                A0[r * P + c4 * 2]     = w0;
                A0[r * P + c4 * 2 + 1] = w1;
            }
            __syncthreads();
            compute_store(aB0, rowbase);
        }
    }
}

// ---------------- CSR gather aggregation: half-warp per node ----------------
template <int WIDTH, bool FINAL>
__global__ void __launch_bounds__(256) agg_kernel(const float* __restrict__ bias,
                                                  float* __restrict__ outp) {
    const int l   = threadIdx.x & 15;
    const int ghw = (blockIdx.x * blockDim.x + threadIdx.x) >> 4;
    const int nhw = (gridDim.x * blockDim.x) >> 4;

    for (int n = ghw; n < NN; n += nhw) {
        const int2 meta = __ldg(&g_meta[n]);
        const int beg = meta.x;
        const int end = meta.x + meta.y;

        if (WIDTH == 128) {
            float accA[8] = {0,0,0,0,0,0,0,0};
            float accB[8] = {0,0,0,0,0,0,0,0};
            int e = beg;
            for (; e + 8 <= end; e += 8) {
                uint4 raw[8];
#pragma unroll
                for (int m = 0; m < 8; m++) {
                    const int s = __ldg(&g_csr_src[e + m]);
                    raw[m] = reinterpret_cast<const uint4*>(g_G + (size_t)s * 128)[l];
                }
#pragma unroll
                for (int m = 0; m < 8; m++) {
                    float* acc = (m & 1) ? accB : accA;
                    const float2 p0 = __half22float2(*reinterpret_cast<const __half2*>(&raw[m].x));
                    const float2 p1 = __half22float2(*reinterpret_cast<const __half2*>(&raw[m].y));
                    const float2 p2 = __half22float2(*reinterpret_cast<const __half2*>(&raw[m].z));
                    const float2 p3 = __half22float2(*reinterpret_cast<const __half2*>(&raw[m].w));
                    acc[0] += p0.x; acc[1] += p0.y; acc[2] += p1.x; acc[3] += p1.y;
                    acc[4] += p2.x; acc[5] += p2.y; acc[6] += p3.x; acc[7] += p3.y;
                }
            }
            if (e < end) {
                uint4 raw[8];
#pragma unroll
                for (int m = 0; m < 8; m++) {
                    const int ee = e + m;
                    const bool valid = ee < end;
                    const int s = __ldg(&g_csr_src[valid ? ee : beg]);
                    uint4 r = reinterpret_cast<const uint4*>(g_G + (size_t)s * 128)[l];
                    raw[m].x = valid ? r.x : 0u;
                    raw[m].y = valid ? r.y : 0u;
                    raw[m].z = valid ? r.z : 0u;
                    raw[m].w = valid ? r.w : 0u;
                }
#pragma unroll
                for (int m = 0; m < 8; m++) {
                    float* acc = (m & 1) ? accB : accA;
                    const float2 p0 = __half22float2(*reinterpret_cast<const __half2*>(&raw[m].x));
                    const float2 p1 = __half22float2(*reinterpret_cast<const __half2*>(&raw[m].y));
                    const float2 p2 = __half22float2(*reinterpret_cast<const __half2*>(&raw[m].z));
                    const float2 p3 = __half22float2(*reinterpret_cast<const __half2*>(&raw[m].w));
                    acc[0] += p0.x; acc[1] += p0.y; acc[2] += p1.x; acc[3] += p1.y;
                    acc[4] += p2.x; acc[5] += p2.y; acc[6] += p3.x; acc[7] += p3.y;
                }
            }
            const float ni = g_norm_in[n];
            const float no = g_norm_out[n];
            const float4 bb0 = reinterpret_cast<const float4*>(bias)[l * 2];
            const float4 bb1 = reinterpret_cast<const float4*>(bias)[l * 2 + 1];
            float r0 = fmaxf(fmaf(accA[0] + accB[0], ni, bb0.x), 0.f) * no;
            float r1 = fmaxf(fmaf(accA[1] + accB[1], ni, bb0.y), 0.f) * no;
            float r2 = fmaxf(fmaf(accA[2] + accB[2], ni, bb0.z), 0.f) * no;
            float r3 = fmaxf(fmaf(accA[3] + accB[3], ni, bb0.w), 0.f) * no;
            float r4 = fmaxf(fmaf(accA[4] + accB[4], ni, bb1.x), 0.f) * no;
            float r5 = fmaxf(fmaf(accA[5] + accB[5], ni, bb1.y), 0.f) * no;
            float r6 = fmaxf(fmaf(accA[6] + accB[6], ni, bb1.z), 0.f) * no;
            float r7 = fmaxf(fmaf(accA[7] + accB[7], ni, bb1.w), 0.f) * no;
            __half2 h0 = __floats2half2_rn(r0, r1);
            __half2 h1 = __floats2half2_rn(r2, r3);
            __half2 h2 = __floats2half2_rn(r4, r5);
            __half2 h3 = __floats2half2_rn(r6, r7);
            uint4 o;
            o.x = *reinterpret_cast<uint32_t*>(&h0);
            o.y = *reinterpret_cast<uint32_t*>(&h1);
            o.z = *reinterpret_cast<uint32_t*>(&h2);
            o.w = *reinterpret_cast<uint32_t*>(&h3);
            reinterpret_cast<uint4*>(g_H + (size_t)n * 128)[l] = o;
        } else {
            float accA[4] = {0,0,0,0};
            float accB[4] = {0,0,0,0};
            int e = beg;
            for (; e + 8 <= end; e += 8) {
                uint2 raw[8];
#pragma unroll
                for (int m = 0; m < 8; m++) {
                    const int s = __ldg(&g_csr_src[e + m]);
                    raw[m] = reinterpret_cast<const uint2*>(g_G + (size_t)s * 64)[l];
                }
#pragma unroll
                for (int m = 0; m < 8; m++) {
                    float* acc = (m & 1) ? accB : accA;
                    const float2 p0 = __half22float2(*reinterpret_cast<const __half2*>(&raw[m].x));
                    const float2 p1 = __half22float2(*reinterpret_cast<const __half2*>(&raw[m].y));
                    acc[0] += p0.x; acc[1] += p0.y; acc[2] += p1.x; acc[3] += p1.y;
                }
            }
            if (e < end) {
                uint2 raw[8];
#pragma unroll
                for (int m = 0; m < 8; m++) {
                    const int ee = e + m;
                    const bool valid = ee < end;
                    const int s = __ldg(&g_csr_src[valid ? ee : beg]);
                    uint2 r = reinterpret_cast<const uint2*>(g_G + (size_t)s * 64)[l];
                    raw[m].x = valid ? r.x : 0u;
                    raw[m].y = valid ? r.y : 0u;
                }
#pragma unroll
                for (int m = 0; m < 8; m++) {
                    float* acc = (m & 1) ? accB : accA;
                    const float2 p0 = __half22float2(*reinterpret_cast<const __half2*>(&raw[m].x));
                    const float2 p1 = __half22float2(*reinterpret_cast<const __half2*>(&raw[m].y));
                    acc[0] += p0.x; acc[1] += p0.y; acc[2] += p1.x; acc[3] += p1.y;
                }
            }
            const float ni = g_norm_in[n];
            const float4 bb = reinterpret_cast<const float4*>(bias)[l];
            float4 o;
            o.x = fmaf(accA[0] + accB[0], ni, bb.x);
            o.y = fmaf(accA[1] + accB[1], ni, bb.y);
            o.z = fmaf(accA[2] + accB[2], ni, bb.z);
            o.w = fmaf(accA[3] + accB[3], ni, bb.w);
            reinterpret_cast<float4*>(outp + (size_t)n * 64)[l] = o;
        }
    }
}

// ---------------- launch ----------------
extern "C" void kernel_launch(void* const* d_in, const int* in_sizes, int n_in,
                              void* d_out, int out_size) {
    const float* feat = (const float*)d_in[0];
    const int*   src  = (const int*)d_in[1];
    const int*   dst  = (const int*)d_in[2];
    const float* W0   = (const float*)d_in[3];
    const float* b0   = (const float*)d_in[4];
    const float* W1   = (const float*)d_in[5];
    const float* b1   = (const float*)d_in[6];
    const float* W2   = (const float*)d_in[7];
    const float* b2   = (const float*)d_in[8];
    float* out = (float*)d_out;

    const int SM128_L0 = (128 * 68 + 64 * 68) * 4;      // 52224 B (1 A buffer)
    const int SM128_P  = (128 * 68 + 2 * 64 * 68) * 4;  // 69632 B (2 A buffers)
    const int SM64_P   = (64 * 68 + 2 * 64 * 68) * 4;   // 52224 B
    cudaFuncSetAttribute(mma_gemm<128, false>, cudaFuncAttributeMaxDynamicSharedMemorySize, SM128_L0);
    cudaFuncSetAttribute(mma_gemm<128, true>,  cudaFuncAttributeMaxDynamicSharedMemorySize, SM128_P);
    cudaFuncSetAttribute(mma_gemm<64,  true>,  cudaFuncAttributeMaxDynamicSharedMemorySize, SM64_P);

    const int T = 256;
    const int GGRID = 444;   // 3 CTAs/SM
    const int AGRID = 1184;

    // 1-3: histogram + norms
    zero_kernel<<<(NN + T - 1) / T, T>>>();
    hist_kernel<<<(NE + T - 1) / T, T>>>(src, dst);
    norm_kernel<<<(NN + T - 1) / T, T>>>();
    // 4: layer-0 GEMM (profiled slot) — fused normalize+convert A path
    mma_gemm<128, false><<<GGRID, T, SM128_L0>>>(feat, W0);
    // 5-8: CSR build
    scan1_kernel<<<NBLK_SCAN, 256>>>();
    scan2_kernel<<<1, 256>>>();
    scan3_kernel<<<(NN + T - 1) / T, T>>>();
    place_kernel<<<(NE + T - 1) / T, T>>>(src, dst);

    // layer 0 aggregation -> g_H (fp16)
    agg_kernel<128, false><<<AGRID, T>>>(b0, nullptr);

    // layer 1 (pipelined A from g_H)
    mma_gemm<128, true><<<GGRID, T, SM128_P>>>(nullptr, W1);
    agg_kernel<128, false><<<AGRID, T>>>(b1, nullptr);

    // layer 2 (64-wide, pipelined)
    mma_gemm<64, true><<<GGRID, T, SM64_P>>>(nullptr, W2);
    agg_kernel<64, true><<<AGRID, T>>>(b2, out);
}

// round 14
// speedup vs baseline: 1.0766x; 1.0061x over previous
#include <cuda_runtime.h>
#include <cuda_fp16.h>
#include <cstdint>
#include <cstddef>

#define NN 170000
#define NE 1200000
#define NBLK_SCAN 167        // ceil(NN / 1024)

// ---------------- device scratch (allocation-free) ----------------
__device__ __half g_G[(size_t)NN * 128];  // GEMM output (fp16)
__device__ __half g_H[(size_t)NN * 128];  // GEMM A source (fp16)
__device__ int    g_deg_out[NN];
__device__ int    g_cnt[NN];
__device__ int    g_off[NN];
__device__ int2   g_meta[NN];             // {offset, count}
__device__ int    g_fill[NN];
__device__ int    g_bsum[NBLK_SCAN];
__device__ float  g_norm_out[NN];
__device__ float  g_norm_in[NN];
__device__ int    g_csr_src[NE];

// ---------------- CSR build ----------------
__global__ void zero_kernel() {
    int i = blockIdx.x * blockDim.x + threadIdx.x;
    if (i < NN) { g_deg_out[i] = 0; g_cnt[i] = 0; g_fill[i] = 0; }
}

__global__ void hist_kernel(const int* __restrict__ src, const int* __restrict__ dst) {
    int e = blockIdx.x * blockDim.x + threadIdx.x;
    if (e < NE) {
        atomicAdd(&g_deg_out[src[e]], 1);
        atomicAdd(&g_cnt[dst[e]], 1);
    }
}

__global__ void scan1_kernel() {
    __shared__ int sh[256];
    const int t = threadIdx.x;
    const int base = blockIdx.x * 1024 + t * 4;
    int c0 = 0, c1 = 0, c2 = 0, c3 = 0;
    if (base + 3 < NN) {
        int4 v = *reinterpret_cast<const int4*>(&g_cnt[base]);
        c0 = v.x; c1 = v.y; c2 = v.z; c3 = v.w;
    } else {
        if (base     < NN) c0 = g_cnt[base];
        if (base + 1 < NN) c1 = g_cnt[base + 1];
        if (base + 2 < NN) c2 = g_cnt[base + 2];
        if (base + 3 < NN) c3 = g_cnt[base + 3];
    }
    const int mysum = c0 + c1 + c2 + c3;
    sh[t] = mysum;
    __syncthreads();
    for (int off = 1; off < 256; off <<= 1) {
        int v = (t >= off) ? sh[t - off] : 0;
        __syncthreads();
        sh[t] += v;
        __syncthreads();
    }
    const int excl = sh[t] - mysum;
    if (t == 255) g_bsum[blockIdx.x] = sh[255];
    if (base     < NN) g_off[base]     = excl;
    if (base + 1 < NN) g_off[base + 1] = excl + c0;
    if (base + 2 < NN) g_off[base + 2] = excl + c0 + c1;
    if (base + 3 < NN) g_off[base + 3] = excl + c0 + c1 + c2;
}

__global__ void scan2_kernel() {
    __shared__ int sh[256];
    const int t = threadIdx.x;
    int v = (t < NBLK_SCAN) ? g_bsum[t] : 0;
    sh[t] = v;
    __syncthreads();
    for (int off = 1; off < 256; off <<= 1) {
        int u = (t >= off) ? sh[t - off] : 0;
        __syncthreads();
        sh[t] += u;
        __syncthreads();
    }
    if (t < NBLK_SCAN) g_bsum[t] = sh[t] - v;
}

// offsets + meta + norms (folded; GEMM0 depends on norms so this runs before it)
__global__ void scan3_kernel() {
    int i = blockIdx.x * blockDim.x + threadIdx.x;
    if (i < NN) {
        const int off = g_off[i] + g_bsum[i >> 10];
        g_off[i] = off;
        const int cnt = g_cnt[i];
        g_meta[i] = make_int2(off, cnt);
        int din  = cnt;          if (din  < 1) din  = 1;
        int dout = g_deg_out[i]; if (dout < 1) dout = 1;
        g_norm_in[i]  = rsqrtf((float)din);
        g_norm_out[i] = rsqrtf((float)dout);
    }
}

__global__ void place_kernel(const int* __restrict__ src, const int* __restrict__ dst) {
    int e = blockIdx.x * blockDim.x + threadIdx.x;
    if (e < NE) {
        const int d = dst[e];
        const int pos = g_off[d] + atomicAdd(&g_fill[d], 1);
        g_csr_src[pos] = src[e];
    }
}

// ---------------- mma / ldmatrix / cp.async helpers ----------------
__device__ __forceinline__ void mma_f16(float* c, const uint32_t* a, uint32_t b0, uint32_t b1) {
    asm volatile(
        "mma.sync.aligned.m16n8k16.row.col.f32.f16.f16.f32 "
        "{%0,%1,%2,%3}, {%4,%5,%6,%7}, {%8,%9}, {%0,%1,%2,%3};"
        : "+f"(c[0]), "+f"(c[1]), "+f"(c[2]), "+f"(c[3])
        : "r"(a[0]), "r"(a[1]), "r"(a[2]), "r"(a[3]), "r"(b0), "r"(b1));
}

__device__ __forceinline__ void ldsm_x4(uint32_t* r, uint32_t addr) {
    asm volatile("ldmatrix.sync.aligned.m8n8.x4.shared.b16 {%0,%1,%2,%3}, [%4];"
                 : "=r"(r[0]), "=r"(r[1]), "=r"(r[2]), "=r"(r[3]) : "r"(addr));
}

__device__ __forceinline__ void ldsm_x2(uint32_t& r0, uint32_t& r1, uint32_t addr) {
    asm volatile("ldmatrix.sync.aligned.m8n8.x2.shared.b16 {%0,%1}, [%2];"
                 : "=r"(r0), "=r"(r1) : "r"(addr));
}

__device__ __forceinline__ void cp16(uint32_t dst, const void* src) {
    asm volatile("cp.async.cg.shared.global [%0], [%1], 16;" :: "r"(dst), "l"(src));
}
__device__ __forceinline__ void cp_commit() { asm volatile("cp.async.commit_group;"); }
__device__ __forceinline__ void cp_wait1()  { asm volatile("cp.async.wait_group 1;"); }
__device__ __forceinline__ void cp_wait0()  { asm volatile("cp.async.wait_group 0;"); }

// ---------------- tensor-core GEMM (fp16 m16n8k16 + ldmatrix) ----------------
// SRC_H=false (layer 0): cp.async fp32 staging pipeline — stage tile fp32, convert to
//   fp16 A in smem, overlap next tile's staging load with compute. 1 staging buffer.
// SRC_H=true (layers 1,2): cp.async double-buffered fp16 bit-copy from g_H.
template <int OUTD, bool SRC_H>
__global__ void __launch_bounds__(256, 2) mma_gemm(const float* __restrict__ X,
                                                   const float* __restrict__ W) {
    constexpr int NF = OUTD / 32;
    constexpr int P  = 68;
    extern __shared__ uint32_t smw[];
    uint32_t* Wh = smw;                    // [OUTD][P]
    uint32_t* A0 = Wh + OUTD * P;          // [64][P]
    uint32_t* A1 = A0 + 64 * P;            // [64][P]  (SRC_H) | fp32 staging (L0, 2048 words... )
    float*    S  = reinterpret_cast<float*>(A1);  // L0: [64][128] fp32 staging (32KB)

    const int tid  = threadIdx.x;
    const int lane = tid & 31;
    const int warp = tid >> 5;
    const int mw   = warp & 1;
    const int nw   = warp >> 1;
    const int g    = lane >> 2;
    const int tg   = lane & 3;

    for (int i = tid; i < 64 * OUTD; i += 256) {
        const int kp = i / OUTD, n = i - kp * OUTD;
        const float w0 = W[(size_t)(kp * 2)     * OUTD + n];
        const float w1 = W[(size_t)(kp * 2 + 1) * OUTD + n];
        __half2 h = __floats2half2_rn(w0, w1);
        Wh[n * P + kp] = *reinterpret_cast<uint32_t*>(&h);
    }

    const uint32_t aB0 = (uint32_t)__cvta_generic_to_shared(A0);
    const uint32_t aB1 = (uint32_t)__cvta_generic_to_shared(A1);
    const uint32_t sB  = (uint32_t)__cvta_generic_to_shared(S);
    const uint32_t wBase = (uint32_t)__cvta_generic_to_shared(Wh);
    const int sel = lane >> 3;
    const int li  = lane & 7;
    uint32_t aOff[2];
#pragma unroll
    for (int mf = 0; mf < 2; mf++) {
        const int row = mw * 32 + mf * 16 + (sel & 1) * 8 + li;
        aOff[mf] = (uint32_t)((row * P + (sel >> 1) * 4) * 4);
    }
    uint32_t bAddr[NF];
#pragma unroll
    for (int nf = 0; nf < NF; nf++) {
        const int n = nw * (NF * 8) + nf * 8 + li;
        bAddr[nf] = wBase + (uint32_t)((n * P + (sel & 1) * 4) * 4);
    }

    const int ntiles = (NN + 63) / 64;

    auto compute_store = [&](uint32_t aBase, int rowbase) {
        float acc[2][NF][4];
#pragma unroll
        for (int mf = 0; mf < 2; mf++)
#pragma unroll
            for (int nf = 0; nf < NF; nf++)
#pragma unroll
                for (int j = 0; j < 4; j++) acc[mf][nf][j] = 0.f;

#pragma unroll
        for (int ks = 0; ks < 8; ks++) {
            uint32_t a[2][4];
            ldsm_x4(a[0], aBase + aOff[0] + ks * 32);
            ldsm_x4(a[1], aBase + aOff[1] + ks * 32);
            uint32_t b[NF][2];
#pragma unroll
            for (int nf = 0; nf < NF; nf++)
                ldsm_x2(b[nf][0], b[nf][1], bAddr[nf] + ks * 32);
#pragma unroll
            for (int nf = 0; nf < NF; nf++)
#pragma unroll
                for (int mf = 0; mf < 2; mf++)
                    mma_f16(acc[mf][nf], a[mf], b[nf][0], b[nf][1]);
        }

#pragma unroll
        for (int mf = 0; mf < 2; mf++) {
            const int r0 = rowbase + mw * 32 + mf * 16 + g;
#pragma unroll
            for (int nf = 0; nf < NF; nf++) {
                const int col = nw * (NF * 8) + nf * 8 + tg * 2;
                if (r0 < NN) {
                    __half2 h = __floats2half2_rn(acc[mf][nf][0], acc[mf][nf][1]);
                    *reinterpret_cast<__half2*>(&g_G[(size_t)r0 * OUTD + col]) = h;
                }
                if (r0 + 8 < NN) {
                    __half2 h = __floats2half2_rn(acc[mf][nf][2], acc[mf][nf][3]);
                    *reinterpret_cast<__half2*>(&g_G[(size_t)(r0 + 8) * OUTD + col]) = h;
                }
            }
        }
    };

    if (SRC_H) {
        // fp16 bit-copy, double buffer
        auto prefetch = [&](int tile, uint32_t bufBase) {
#pragma unroll
            for (int j = 0; j < 4; j++) {
                const int id = tid + j * 256;
                const int r = id >> 4, c16 = id & 15;
                int row = tile * 64 + r;
                if (row >= NN) row = NN - 1;
                cp16(bufBase + (uint32_t)((r * P + c16 * 4) * 4),
                     g_H + (size_t)row * 128 + c16 * 8);
            }
        };

        int t = blockIdx.x;
        if (t < ntiles) prefetch(t, aB0);
        cp_commit();
        int parity = 0;
        for (; t < ntiles; t += gridDim.x) {
            const int tn = t + gridDim.x;
            if (tn < ntiles) prefetch(tn, parity ? aB0 : aB1);
            cp_commit();
            cp_wait1();
            __syncthreads();
            compute_store(parity ? aB1 : aB0, t * 64);
            __syncthreads();
            parity ^= 1;
        }
    } else {
        // layer 0: fp32 staging pipeline (single staging buffer S)
        // stage tile t: 64 rows x 512B; each thread 8 x 16B cp.async
        auto stage = [&](int tile) {
#pragma unroll
            for (int j = 0; j < 8; j++) {
                const int id = tid + j * 256;
                const int r = id >> 5, c16 = id & 31;   // 32 x 16B per row
                int row = tile * 64 + r;
                if (row >= NN) row = NN - 1;
                cp16(sB + (uint32_t)((r * 128 + c16 * 4) * 4),
                     X + (size_t)row * 128 + c16 * 4);
            }
        };

        int t = blockIdx.x;
        if (t < ntiles) stage(t);
        cp_commit();
        for (; t < ntiles; t += gridDim.x) {
            cp_wait0();
            __syncthreads();
            // convert staging fp32 -> A0 fp16 (with norm_out scale)
            const int rowbase = t * 64;
            for (int i = tid; i < 64 * 32; i += 256) {
                const int r = i >> 5, c4 = i & 31;
                const int row = rowbase + r;
                uint32_t w0 = 0, w1 = 0;
                if (row < NN) {
                    const float4 v = *reinterpret_cast<const float4*>(&S[r * 128 + c4 * 4]);
                    const float no = g_norm_out[row];
                    __half2 h0 = __floats2half2_rn(v.x * no, v.y * no);
                    __half2 h1 = __floats2half2_rn(v.z * no, v.w * no);
                    w0 = *reinterpret_cast<uint32_t*>(&h0);
                    w1 = *reinterpret_cast<uint32_t*>(&h1);
                }
                A0[r * P + c4 * 2]     = w0;
                A0[r * P + c4 * 2 + 1] = w1;
            }
            __syncthreads();   // A0 ready, S consumed
            const int tn = t + gridDim.x;
            if (tn < ntiles) stage(tn);   // overlaps with compute below
            cp_commit();
            compute_store(aB0, rowbase);
            __syncthreads();   // protect A0 from next iteration's convert
        }
    }
}

// ---------------- CSR gather aggregation: half-warp per node ----------------
template <int WIDTH, bool FINAL>
__global__ void __launch_bounds__(256) agg_kernel(const float* __restrict__ bias,
                                                  float* __restrict__ outp) {
    const int l   = threadIdx.x & 15;
    const int ghw = (blockIdx.x * blockDim.x + threadIdx.x) >> 4;
    const int nhw = (gridDim.x * blockDim.x) >> 4;

    for (int n = ghw; n < NN; n += nhw) {
        const int2 meta = __ldg(&g_meta[n]);
        const int beg = meta.x;
        const int end = meta.x + meta.y;

        if (WIDTH == 128) {
            float accA[8] = {0,0,0,0,0,0,0,0};
            float accB[8] = {0,0,0,0,0,0,0,0};
            int e = beg;
            for (; e + 8 <= end; e += 8) {
                uint4 raw[8];
#pragma unroll
                for (int m = 0; m < 8; m++) {
                    const int s = __ldg(&g_csr_src[e + m]);
                    raw[m] = reinterpret_cast<const uint4*>(g_G + (size_t)s * 128)[l];
                }
#pragma unroll
                for (int m = 0; m < 8; m++) {
                    float* acc = (m & 1) ? accB : accA;
                    const float2 p0 = __half22float2(*reinterpret_cast<const __half2*>(&raw[m].x));
                    const float2 p1 = __half22float2(*reinterpret_cast<const __half2*>(&raw[m].y));
                    const float2 p2 = __half22float2(*reinterpret_cast<const __half2*>(&raw[m].z));
                    const float2 p3 = __half22float2(*reinterpret_cast<const __half2*>(&raw[m].w));
                    acc[0] += p0.x; acc[1] += p0.y; acc[2] += p1.x; acc[3] += p1.y;
                    acc[4] += p2.x; acc[5] += p2.y; acc[6] += p3.x; acc[7] += p3.y;
                }
            }
            if (e < end) {
                uint4 raw[8];
#pragma unroll
                for (int m = 0; m < 8; m++) {
                    const int ee = e + m;
                    const bool valid = ee < end;
                    const int s = __ldg(&g_csr_src[valid ? ee : beg]);
                    uint4 r = reinterpret_cast<const uint4*>(g_G + (size_t)s * 128)[l];
                    raw[m].x = valid ? r.x : 0u;
                    raw[m].y = valid ? r.y : 0u;
                    raw[m].z = valid ? r.z : 0u;
                    raw[m].w = valid ? r.w : 0u;
                }
#pragma unroll
                for (int m = 0; m < 8; m++) {
                    float* acc = (m & 1) ? accB : accA;
                    const float2 p0 = __half22float2(*reinterpret_cast<const __half2*>(&raw[m].x));
                    const float2 p1 = __half22float2(*reinterpret_cast<const __half2*>(&raw[m].y));
                    const float2 p2 = __half22float2(*reinterpret_cast<const __half2*>(&raw[m].z));
                    const float2 p3 = __half22float2(*reinterpret_cast<const __half2*>(&raw[m].w));
                    acc[0] += p0.x; acc[1] += p0.y; acc[2] += p1.x; acc[3] += p1.y;
                    acc[4] += p2.x; acc[5] += p2.y; acc[6] += p3.x; acc[7] += p3.y;
                }
            }
            const float ni = g_norm_in[n];
            const float no = g_norm_out[n];
            const float4 bb0 = reinterpret_cast<const float4*>(bias)[l * 2];
            const float4 bb1 = reinterpret_cast<const float4*>(bias)[l * 2 + 1];
            float r0 = fmaxf(fmaf(accA[0] + accB[0], ni, bb0.x), 0.f) * no;
            float r1 = fmaxf(fmaf(accA[1] + accB[1], ni, bb0.y), 0.f) * no;
            float r2 = fmaxf(fmaf(accA[2] + accB[2], ni, bb0.z), 0.f) * no;
            float r3 = fmaxf(fmaf(accA[3] + accB[3], ni, bb0.w), 0.f) * no;
            float r4 = fmaxf(fmaf(accA[4] + accB[4], ni, bb1.x), 0.f) * no;
            float r5 = fmaxf(fmaf(accA[5] + accB[5], ni, bb1.y), 0.f) * no;
            float r6 = fmaxf(fmaf(accA[6] + accB[6], ni, bb1.z), 0.f) * no;
            float r7 = fmaxf(fmaf(accA[7] + accB[7], ni, bb1.w), 0.f) * no;
            __half2 h0 = __floats2half2_rn(r0, r1);
            __half2 h1 = __floats2half2_rn(r2, r3);
            __half2 h2 = __floats2half2_rn(r4, r5);
            __half2 h3 = __floats2half2_rn(r6, r7);
            uint4 o;
            o.x = *reinterpret_cast<uint32_t*>(&h0);
            o.y = *reinterpret_cast<uint32_t*>(&h1);
            o.z = *reinterpret_cast<uint32_t*>(&h2);
            o.w = *reinterpret_cast<uint32_t*>(&h3);
            reinterpret_cast<uint4*>(g_H + (size_t)n * 128)[l] = o;
        } else {
            float accA[4] = {0,0,0,0};
            float accB[4] = {0,0,0,0};
            int e = beg;
            for (; e + 8 <= end; e += 8) {
                uint2 raw[8];
#pragma unroll
                for (int m = 0; m < 8; m++) {
                    const int s = __ldg(&g_csr_src[e + m]);
                    raw[m] = reinterpret_cast<const uint2*>(g_G + (size_t)s * 64)[l];
                }
#pragma unroll
                for (int m = 0; m < 8; m++) {
                    float* acc = (m & 1) ? accB : accA;
                    const float2 p0 = __half22float2(*reinterpret_cast<const __half2*>(&raw[m].x));
                    const float2 p1 = __half22float2(*reinterpret_cast<const __half2*>(&raw[m].y));
                    acc[0] += p0.x; acc[1] += p0.y; acc[2] += p1.x; acc[3] += p1.y;
                }
            }
            if (e < end) {
                uint2 raw[8];
#pragma unroll
                for (int m = 0; m < 8; m++) {
                    const int ee = e + m;
                    const bool valid = ee < end;
                    const int s = __ldg(&g_csr_src[valid ? ee : beg]);
                    uint2 r = reinterpret_cast<const uint2*>(g_G + (size_t)s * 64)[l];
                    raw[m].x = valid ? r.x : 0u;
                    raw[m].y = valid ? r.y : 0u;
                }
#pragma unroll
                for (int m = 0; m < 8; m++) {
                    float* acc = (m & 1) ? accB : accA;
                    const float2 p0 = __half22float2(*reinterpret_cast<const __half2*>(&raw[m].x));
                    const float2 p1 = __half22float2(*reinterpret_cast<const __half2*>(&raw[m].y));
                    acc[0] += p0.x; acc[1] += p0.y; acc[2] += p1.x; acc[3] += p1.y;
                }
            }
            const float ni = g_norm_in[n];
            const float4 bb = reinterpret_cast<const float4*>(bias)[l];
            float4 o;
            o.x = fmaf(accA[0] + accB[0], ni, bb.x);
            o.y = fmaf(accA[1] + accB[1], ni, bb.y);
            o.z = fmaf(accA[2] + accB[2], ni, bb.z);
            o.w = fmaf(accA[3] + accB[3], ni, bb.w);
            reinterpret_cast<float4*>(outp + (size_t)n * 64)[l] = o;
        }
    }
}

// ---------------- launch ----------------
extern "C" void kernel_launch(void* const* d_in, const int* in_sizes, int n_in,
                              void* d_out, int out_size) {
    const float* feat = (const float*)d_in[0];
    const int*   src  = (const int*)d_in[1];
    const int*   dst  = (const int*)d_in[2];
    const float* W0   = (const float*)d_in[3];
    const float* b0   = (const float*)d_in[4];
    const float* W1   = (const float*)d_in[5];
    const float* b1   = (const float*)d_in[6];
    const float* W2   = (const float*)d_in[7];
    const float* b2   = (const float*)d_in[8];
    float* out = (float*)d_out;

    const int SM128_L0 = (128 * 68 + 64 * 68) * 4 + 64 * 128 * 4;  // 85 KB (W + A + fp32 staging)
    const int SM128_P  = (128 * 68 + 2 * 64 * 68) * 4;             // 69632 B
    const int SM64_P   = (64 * 68 + 2 * 64 * 68) * 4;              // 52224 B
    cudaFuncSetAttribute(mma_gemm<128, false>, cudaFuncAttributeMaxDynamicSharedMemorySize, SM128_L0);
    cudaFuncSetAttribute(mma_gemm<128, true>,  cudaFuncAttributeMaxDynamicSharedMemorySize, SM128_P);
    cudaFuncSetAttribute(mma_gemm<64,  true>,  cudaFuncAttributeMaxDynamicSharedMemorySize, SM64_P);

    const int T = 256;
    const int GGRID = 296;   // 2 CTAs/SM (L0 smem-bound; same grid reused for all GEMMs)
    const int AGRID = 1184;

    // CSR build + norms (scan3 now also produces norms, needed by GEMM0)
    zero_kernel<<<(NN + T - 1) / T, T>>>();
    hist_kernel<<<(NE + T - 1) / T, T>>>(src, dst);
    scan1_kernel<<<NBLK_SCAN, 256>>>();
    scan2_kernel<<<1, 256>>>();
    scan3_kernel<<<(NN + T - 1) / T, T>>>();
    place_kernel<<<(NE + T - 1) / T, T>>>(src, dst);

    // layer 0: staged-fp32 pipelined GEMM, then aggregation
    mma_gemm<128, false><<<GGRID, T, SM128_L0>>>(feat, W0);
    agg_kernel<128, false><<<AGRID, T>>>(b0, nullptr);

    // layer 1 (pipelined fp16 A from g_H)
    mma_gemm<128, true><<<GGRID, T, SM128_P>>>(nullptr, W1);
    agg_kernel<128, false><<<AGRID, T>>>(b1, nullptr);

    // layer 2 (64-wide, pipelined)
    mma_gemm<64, true><<<GGRID, T, SM64_P>>>(nullptr, W2);
    agg_kernel<64, true><<<AGRID, T>>>(b2, out);
}

// round 15
// speedup vs baseline: 1.0935x; 1.0157x over previous
#include <cuda_runtime.h>
#include <cuda_fp16.h>
#include <cstdint>
#include <cstddef>

#define NN 170000
#define NE 1200000
#define NBLK_SCAN 167        // ceil(NN / 1024)

// ---------------- device scratch (allocation-free) ----------------
__device__ __half g_G[(size_t)NN * 128];  // GEMM output (fp16)
__device__ __half g_H[(size_t)NN * 128];  // GEMM A source (fp16)
__device__ int    g_deg_out[NN];
__device__ int    g_cnt[NN];
__device__ int    g_off[NN];
__device__ int2   g_meta[NN];             // {offset, count}
__device__ int    g_fill[NN];
__device__ int    g_bsum[NBLK_SCAN];
__device__ float  g_norm_out[NN];
__device__ float  g_norm_in[NN];
__device__ int    g_csr_src[NE];

// ---------------- CSR build ----------------
__global__ void zero_kernel() {
    int i = blockIdx.x * blockDim.x + threadIdx.x;
    if (i < NN) { g_deg_out[i] = 0; g_cnt[i] = 0; g_fill[i] = 0; }
}

__global__ void hist_kernel(const int* __restrict__ src, const int* __restrict__ dst) {
    int e = blockIdx.x * blockDim.x + threadIdx.x;
    if (e < NE) {
        atomicAdd(&g_deg_out[src[e]], 1);
        atomicAdd(&g_cnt[dst[e]], 1);
    }
}

__global__ void scan1_kernel() {
    __shared__ int sh[256];
    const int t = threadIdx.x;
    const int base = blockIdx.x * 1024 + t * 4;
    int c0 = 0, c1 = 0, c2 = 0, c3 = 0;
    if (base + 3 < NN) {
        int4 v = *reinterpret_cast<const int4*>(&g_cnt[base]);
        c0 = v.x; c1 = v.y; c2 = v.z; c3 = v.w;
    } else {
        if (base     < NN) c0 = g_cnt[base];
        if (base + 1 < NN) c1 = g_cnt[base + 1];
        if (base + 2 < NN) c2 = g_cnt[base + 2];
        if (base + 3 < NN) c3 = g_cnt[base + 3];
    }
    const int mysum = c0 + c1 + c2 + c3;
    sh[t] = mysum;
    __syncthreads();
    for (int off = 1; off < 256; off <<= 1) {
        int v = (t >= off) ? sh[t - off] : 0;
        __syncthreads();
        sh[t] += v;
        __syncthreads();
    }
    const int excl = sh[t] - mysum;
    if (t == 255) g_bsum[blockIdx.x] = sh[255];
    if (base     < NN) g_off[base]     = excl;
    if (base + 1 < NN) g_off[base + 1] = excl + c0;
    if (base + 2 < NN) g_off[base + 2] = excl + c0 + c1;
    if (base + 3 < NN) g_off[base + 3] = excl + c0 + c1 + c2;
}

__global__ void scan2_kernel() {
    __shared__ int sh[256];
    const int t = threadIdx.x;
    int v = (t < NBLK_SCAN) ? g_bsum[t] : 0;
    sh[t] = v;
    __syncthreads();
    for (int off = 1; off < 256; off <<= 1) {
        int u = (t >= off) ? sh[t - off] : 0;
        __syncthreads();
        sh[t] += u;
        __syncthreads();
    }
    if (t < NBLK_SCAN) g_bsum[t] = sh[t] - v;
}

// offsets + meta + norms (GEMM0 depends on norms; runs before it)
__global__ void scan3_kernel() {
    int i = blockIdx.x * blockDim.x + threadIdx.x;
    if (i < NN) {
        const int off = g_off[i] + g_bsum[i >> 10];
        g_off[i] = off;
        const int cnt = g_cnt[i];
        g_meta[i] = make_int2(off, cnt);
        int din  = cnt;          if (din  < 1) din  = 1;
        int dout = g_deg_out[i]; if (dout < 1) dout = 1;
        g_norm_in[i]  = rsqrtf((float)din);
        g_norm_out[i] = rsqrtf((float)dout);
    }
}

__global__ void place_kernel(const int* __restrict__ src, const int* __restrict__ dst) {
    int e = blockIdx.x * blockDim.x + threadIdx.x;
    if (e < NE) {
        const int d = dst[e];
        const int pos = g_off[d] + atomicAdd(&g_fill[d], 1);
        g_csr_src[pos] = src[e];
    }
}

// ---------------- mma / ldmatrix / cp.async helpers ----------------
__device__ __forceinline__ void mma_f16(float* c, const uint32_t* a, uint32_t b0, uint32_t b1) {
    asm volatile(
        "mma.sync.aligned.m16n8k16.row.col.f32.f16.f16.f32 "
        "{%0,%1,%2,%3}, {%4,%5,%6,%7}, {%8,%9}, {%0,%1,%2,%3};"
        : "+f"(c[0]), "+f"(c[1]), "+f"(c[2]), "+f"(c[3])
        : "r"(a[0]), "r"(a[1]), "r"(a[2]), "r"(a[3]), "r"(b0), "r"(b1));
}

__device__ __forceinline__ void ldsm_x4(uint32_t* r, uint32_t addr) {
    asm volatile("ldmatrix.sync.aligned.m8n8.x4.shared.b16 {%0,%1,%2,%3}, [%4];"
                 : "=r"(r[0]), "=r"(r[1]), "=r"(r[2]), "=r"(r[3]) : "r"(addr));
}

__device__ __forceinline__ void ldsm_x2(uint32_t& r0, uint32_t& r1, uint32_t addr) {
    asm volatile("ldmatrix.sync.aligned.m8n8.x2.shared.b16 {%0,%1}, [%2];"
                 : "=r"(r0), "=r"(r1) : "r"(addr));
}

__device__ __forceinline__ void cp16(uint32_t dst, const void* src) {
    asm volatile("cp.async.cg.shared.global [%0], [%1], 16;" :: "r"(dst), "l"(src));
}
__device__ __forceinline__ void cp_commit() { asm volatile("cp.async.commit_group;"); }
__device__ __forceinline__ void cp_wait1()  { asm volatile("cp.async.wait_group 1;"); }
__device__ __forceinline__ void cp_wait0()  { asm volatile("cp.async.wait_group 0;"); }

__device__ __forceinline__ uint32_t hadd2u(uint32_t a, uint32_t b) {
    __half2 r = __hadd2(*reinterpret_cast<const __half2*>(&a),
                        *reinterpret_cast<const __half2*>(&b));
    return *reinterpret_cast<uint32_t*>(&r);
}

// ---------------- tensor-core GEMM (fp16 m16n8k16 + ldmatrix) ----------------
// SRC_H=false (layer 0): cp.async fp32 staging pipeline (1 staging buffer).
// SRC_H=true (layers 1,2): cp.async 3-stage fp16 bit-copy pipeline.
template <int OUTD, bool SRC_H>
__global__ void __launch_bounds__(256, 2) mma_gemm(const float* __restrict__ X,
                                                   const float* __restrict__ W) {
    constexpr int NF = OUTD / 32;
    constexpr int P  = 68;
    extern __shared__ uint32_t smw[];
    uint32_t* Wh = smw;                    // [OUTD][P]
    uint32_t* A0 = Wh + OUTD * P;          // [64][P] stage 0
    uint32_t* A1 = A0 + 64 * P;            // stage 1 | L0: fp32 staging lower half
    uint32_t* A2 = A1 + 64 * P;            // stage 2 (SRC_H only)
    float*    S  = reinterpret_cast<float*>(A1);  // L0: [64][128] fp32 staging (32KB)

    const int tid  = threadIdx.x;
    const int lane = tid & 31;
    const int warp = tid >> 5;
    const int mw   = warp & 1;
    const int nw   = warp >> 1;
    const int g    = lane >> 2;
    const int tg   = lane & 3;

    for (int i = tid; i < 64 * OUTD; i += 256) {
        const int kp = i / OUTD, n = i - kp * OUTD;
        const float w0 = W[(size_t)(kp * 2)     * OUTD + n];
        const float w1 = W[(size_t)(kp * 2 + 1) * OUTD + n];
        __half2 h = __floats2half2_rn(w0, w1);
        Wh[n * P + kp] = *reinterpret_cast<uint32_t*>(&h);
    }

    uint32_t aB[3];
    aB[0] = (uint32_t)__cvta_generic_to_shared(A0);
    aB[1] = (uint32_t)__cvta_generic_to_shared(A1);
    aB[2] = (uint32_t)__cvta_generic_to_shared(A2);
    const uint32_t sB  = (uint32_t)__cvta_generic_to_shared(S);
    const uint32_t wBase = (uint32_t)__cvta_generic_to_shared(Wh);
    const int sel = lane >> 3;
    const int li  = lane & 7;
    uint32_t aOff[2];
#pragma unroll
    for (int mf = 0; mf < 2; mf++) {
        const int row = mw * 32 + mf * 16 + (sel & 1) * 8 + li;
        aOff[mf] = (uint32_t)((row * P + (sel >> 1) * 4) * 4);
    }
    uint32_t bAddr[NF];
#pragma unroll
    for (int nf = 0; nf < NF; nf++) {
        const int n = nw * (NF * 8) + nf * 8 + li;
        bAddr[nf] = wBase + (uint32_t)((n * P + (sel & 1) * 4) * 4);
    }

    const int ntiles = (NN + 63) / 64;

    auto compute_store = [&](uint32_t aBase, int rowbase) {
        float acc[2][NF][4];
#pragma unroll
        for (int mf = 0; mf < 2; mf++)
#pragma unroll
            for (int nf = 0; nf < NF; nf++)
#pragma unroll
                for (int j = 0; j < 4; j++) acc[mf][nf][j] = 0.f;

#pragma unroll
        for (int ks = 0; ks < 8; ks++) {
            uint32_t a[2][4];
            ldsm_x4(a[0], aBase + aOff[0] + ks * 32);
            ldsm_x4(a[1], aBase + aOff[1] + ks * 32);
            uint32_t b[NF][2];
#pragma unroll
            for (int nf = 0; nf < NF; nf++)
                ldsm_x2(b[nf][0], b[nf][1], bAddr[nf] + ks * 32);
#pragma unroll
            for (int nf = 0; nf < NF; nf++)
#pragma unroll
                for (int mf = 0; mf < 2; mf++)
                    mma_f16(acc[mf][nf], a[mf], b[nf][0], b[nf][1]);
        }

#pragma unroll
        for (int mf = 0; mf < 2; mf++) {
            const int r0 = rowbase + mw * 32 + mf * 16 + g;
#pragma unroll
            for (int nf = 0; nf < NF; nf++) {
                const int col = nw * (NF * 8) + nf * 8 + tg * 2;
                if (r0 < NN) {
                    __half2 h = __floats2half2_rn(acc[mf][nf][0], acc[mf][nf][1]);
                    *reinterpret_cast<__half2*>(&g_G[(size_t)r0 * OUTD + col]) = h;
                }
                if (r0 + 8 < NN) {
                    __half2 h = __floats2half2_rn(acc[mf][nf][2], acc[mf][nf][3]);
                    *reinterpret_cast<__half2*>(&g_G[(size_t)(r0 + 8) * OUTD + col]) = h;
                }
            }
        }
    };

    if (SRC_H) {
        // fp16 bit-copy, 3-stage pipeline (2 groups in flight)
        auto prefetch = [&](int tile, uint32_t bufBase) {
#pragma unroll
            for (int j = 0; j < 4; j++) {
                const int id = tid + j * 256;
                const int r = id >> 4, c16 = id & 15;
                int row = tile * 64 + r;
                if (row >= NN) row = NN - 1;
                cp16(bufBase + (uint32_t)((r * P + c16 * 4) * 4),
                     g_H + (size_t)row * 128 + c16 * 8);
            }
        };

        const int G = gridDim.x;
        int t = blockIdx.x;
        if (t < ntiles) prefetch(t, aB[0]);
        cp_commit();
        if (t + G < ntiles) prefetch(t + G, aB[1]);
        cp_commit();
        int it = 0;
        for (; t < ntiles; t += G, it++) {
            cp_wait1();
            __syncthreads();
            const int cur = it % 3;
            const int nxt = (it + 2) % 3;
            if (t + 2 * G < ntiles) prefetch(t + 2 * G, aB[nxt]);
            cp_commit();
            compute_store(aB[cur], t * 64);
            __syncthreads();
        }
    } else {
        // layer 0: fp32 staging pipeline (single staging buffer S)
        auto stage = [&](int tile) {
#pragma unroll
            for (int j = 0; j < 8; j++) {
                const int id = tid + j * 256;
                const int r = id >> 5, c16 = id & 31;
                int row = tile * 64 + r;
                if (row >= NN) row = NN - 1;
                cp16(sB + (uint32_t)((r * 128 + c16 * 4) * 4),
                     X + (size_t)row * 128 + c16 * 4);
            }
        };

        int t = blockIdx.x;
        if (t < ntiles) stage(t);
        cp_commit();
        for (; t < ntiles; t += gridDim.x) {
            cp_wait0();
            __syncthreads();
            const int rowbase = t * 64;
            for (int i = tid; i < 64 * 32; i += 256) {
                const int r = i >> 5, c4 = i & 31;
                const int row = rowbase + r;
                uint32_t w0 = 0, w1 = 0;
                if (row < NN) {
                    const float4 v = *reinterpret_cast<const float4*>(&S[r * 128 + c4 * 4]);
                    const float no = g_norm_out[row];
                    __half2 h0 = __floats2half2_rn(v.x * no, v.y * no);
                    __half2 h1 = __floats2half2_rn(v.z * no, v.w * no);
                    w0 = *reinterpret_cast<uint32_t*>(&h0);
                    w1 = *reinterpret_cast<uint32_t*>(&h1);
                }
                A0[r * P + c4 * 2]     = w0;
                A0[r * P + c4 * 2 + 1] = w1;
            }
            __syncthreads();
            const int tn = t + gridDim.x;
            if (tn < ntiles) stage(tn);
            cp_commit();
            compute_store(aB[0], rowbase);
            __syncthreads();
        }
    }
}

// ---------------- CSR gather aggregation: half-warp per node, pairwise HADD2 ----------------
template <int WIDTH, bool FINAL>
__global__ void __launch_bounds__(256) agg_kernel(const float* __restrict__ bias,
                                                  float* __restrict__ outp) {
    const int l   = threadIdx.x & 15;
    const int ghw = (blockIdx.x * blockDim.x + threadIdx.x) >> 4;
    const int nhw = (gridDim.x * blockDim.x) >> 4;

    for (int n = ghw; n < NN; n += nhw) {
        const int2 meta = __ldg(&g_meta[n]);
        const int beg = meta.x;
        const int end = meta.x + meta.y;

        if (WIDTH == 128) {
            float accA[8] = {0,0,0,0,0,0,0,0};
            float accB[8] = {0,0,0,0,0,0,0,0};
            int e = beg;
            for (; e + 8 <= end; e += 8) {
                uint4 raw[8];
#pragma unroll
                for (int m = 0; m < 8; m++) {
                    const int s = __ldg(&g_csr_src[e + m]);
                    raw[m] = reinterpret_cast<const uint4*>(g_G + (size_t)s * 128)[l];
                }
#pragma unroll
                for (int p = 0; p < 4; p++) {
                    uint4 h;
                    h.x = hadd2u(raw[2*p].x, raw[2*p+1].x);
                    h.y = hadd2u(raw[2*p].y, raw[2*p+1].y);
                    h.z = hadd2u(raw[2*p].z, raw[2*p+1].z);
                    h.w = hadd2u(raw[2*p].w, raw[2*p+1].w);
                    float* acc = (p & 1) ? accB : accA;
                    const float2 p0 = __half22float2(*reinterpret_cast<const __half2*>(&h.x));
                    const float2 p1 = __half22float2(*reinterpret_cast<const __half2*>(&h.y));
                    const float2 p2 = __half22float2(*reinterpret_cast<const __half2*>(&h.z));
                    const float2 p3 = __half22float2(*reinterpret_cast<const __half2*>(&h.w));
                    acc[0] += p0.x; acc[1] += p0.y; acc[2] += p1.x; acc[3] += p1.y;
                    acc[4] += p2.x; acc[5] += p2.y; acc[6] += p3.x; acc[7] += p3.y;
                }
            }
            if (e < end) {
                uint4 raw[8];
#pragma unroll
                for (int m = 0; m < 8; m++) {
                    const int ee = e + m;
                    const bool valid = ee < end;
                    const int s = __ldg(&g_csr_src[valid ? ee : beg]);
                    uint4 r = reinterpret_cast<const uint4*>(g_G + (size_t)s * 128)[l];
                    raw[m].x = valid ? r.x : 0u;
                    raw[m].y = valid ? r.y : 0u;
                    raw[m].z = valid ? r.z : 0u;
                    raw[m].w = valid ? r.w : 0u;
                }
#pragma unroll
                for (int p = 0; p < 4; p++) {
                    uint4 h;
                    h.x = hadd2u(raw[2*p].x, raw[2*p+1].x);
                    h.y = hadd2u(raw[2*p].y, raw[2*p+1].y);
                    h.z = hadd2u(raw[2*p].z, raw[2*p+1].z);
                    h.w = hadd2u(raw[2*p].w, raw[2*p+1].w);
                    float* acc = (p & 1) ? accB : accA;
                    const float2 p0 = __half22float2(*reinterpret_cast<const __half2*>(&h.x));
                    const float2 p1 = __half22float2(*reinterpret_cast<const __half2*>(&h.y));
                    const float2 p2 = __half22float2(*reinterpret_cast<const __half2*>(&h.z));
                    const float2 p3 = __half22float2(*reinterpret_cast<const __half2*>(&h.w));
                    acc[0] += p0.x; acc[1] += p0.y; acc[2] += p1.x; acc[3] += p1.y;
                    acc[4] += p2.x; acc[5] += p2.y; acc[6] += p3.x; acc[7] += p3.y;
                }
            }
            const float ni = g_norm_in[n];
            const float no = g_norm_out[n];
            const float4 bb0 = reinterpret_cast<const float4*>(bias)[l * 2];
            const float4 bb1 = reinterpret_cast<const float4*>(bias)[l * 2 + 1];
            float r0 = fmaxf(fmaf(accA[0] + accB[0], ni, bb0.x), 0.f) * no;
            float r1 = fmaxf(fmaf(accA[1] + accB[1], ni, bb0.y), 0.f) * no;
            float r2 = fmaxf(fmaf(accA[2] + accB[2], ni, bb0.z), 0.f) * no;
            float r3 = fmaxf(fmaf(accA[3] + accB[3], ni, bb0.w), 0.f) * no;
            float r4 = fmaxf(fmaf(accA[4] + accB[4], ni, bb1.x), 0.f) * no;
            float r5 = fmaxf(fmaf(accA[5] + accB[5], ni, bb1.y), 0.f) * no;
            float r6 = fmaxf(fmaf(accA[6] + accB[6], ni, bb1.z), 0.f) * no;
            float r7 = fmaxf(fmaf(accA[7] + accB[7], ni, bb1.w), 0.f) * no;
            __half2 h0 = __floats2half2_rn(r0, r1);
            __half2 h1 = __floats2half2_rn(r2, r3);
            __half2 h2 = __floats2half2_rn(r4, r5);
            __half2 h3 = __floats2half2_rn(r6, r7);
            uint4 o;
            o.x = *reinterpret_cast<uint32_t*>(&h0);
            o.y = *reinterpret_cast<uint32_t*>(&h1);
            o.z = *reinterpret_cast<uint32_t*>(&h2);
            o.w = *reinterpret_cast<uint32_t*>(&h3);
            reinterpret_cast<uint4*>(g_H + (size_t)n * 128)[l] = o;
        } else {
            float accA[4] = {0,0,0,0};
            float accB[4] = {0,0,0,0};
            int e = beg;
            for (; e + 8 <= end; e += 8) {
                uint2 raw[8];
#pragma unroll
                for (int m = 0; m < 8; m++) {
                    const int s = __ldg(&g_csr_src[e + m]);
                    raw[m] = reinterpret_cast<const uint2*>(g_G + (size_t)s * 64)[l];
                }
#pragma unroll
                for (int p = 0; p < 4; p++) {
                    uint2 h;
                    h.x = hadd2u(raw[2*p].x, raw[2*p+1].x);
                    h.y = hadd2u(raw[2*p].y, raw[2*p+1].y);
                    float* acc = (p & 1) ? accB : accA;
                    const float2 p0 = __half22float2(*reinterpret_cast<const __half2*>(&h.x));
                    const float2 p1 = __half22float2(*reinterpret_cast<const __half2*>(&h.y));
                    acc[0] += p0.x; acc[1] += p0.y; acc[2] += p1.x; acc[3] += p1.y;
                }
            }
            if (e < end) {
                uint2 raw[8];
#pragma unroll
                for (int m = 0; m < 8; m++) {
                    const int ee = e + m;
                    const bool valid = ee < end;
                    const int s = __ldg(&g_csr_src[valid ? ee : beg]);
                    uint2 r = reinterpret_cast<const uint2*>(g_G + (size_t)s * 64)[l];
                    raw[m].x = valid ? r.x : 0u;
                    raw[m].y = valid ? r.y : 0u;
                }
#pragma unroll
                for (int p = 0; p < 4; p++) {
                    uint2 h;
                    h.x = hadd2u(raw[2*p].x, raw[2*p+1].x);
                    h.y = hadd2u(raw[2*p].y, raw[2*p+1].y);
                    float* acc = (p & 1) ? accB : accA;
                    const float2 p0 = __half22float2(*reinterpret_cast<const __half2*>(&h.x));
                    const float2 p1 = __half22float2(*reinterpret_cast<const __half2*>(&h.y));
                    acc[0] += p0.x; acc[1] += p0.y; acc[2] += p1.x; acc[3] += p1.y;
                }
            }
            const float ni = g_norm_in[n];
            const float4 bb = reinterpret_cast<const float4*>(bias)[l];
            float4 o;
            o.x = fmaf(accA[0] + accB[0], ni, bb.x);
            o.y = fmaf(accA[1] + accB[1], ni, bb.y);
            o.z = fmaf(accA[2] + accB[2], ni, bb.z);
            o.w = fmaf(accA[3] + accB[3], ni, bb.w);
            reinterpret_cast<float4*>(outp + (size_t)n * 64)[l] = o;
        }
    }
}

// ---------------- launch ----------------
extern "C" void kernel_launch(void* const* d_in, const int* in_sizes, int n_in,
                              void* d_out, int out_size) {
    const float* feat = (const float*)d_in[0];
    const int*   src  = (const int*)d_in[1];
    const int*   dst  = (const int*)d_in[2];
    const float* W0   = (const float*)d_in[3];
    const float* b0   = (const float*)d_in[4];
    const float* W1   = (const float*)d_in[5];
    const float* b1   = (const float*)d_in[6];
    const float* W2   = (const float*)d_in[7];
    const float* b2   = (const float*)d_in[8];
    float* out = (float*)d_out;

    const int SM128_L0 = (128 * 68 + 64 * 68) * 4 + 64 * 128 * 4;  // 85 KB
    const int SM128_P  = (128 * 68 + 3 * 64 * 68) * 4;             // 87040 B
    const int SM64_P   = (64 * 68 + 3 * 64 * 68) * 4;              // 69632 B
    cudaFuncSetAttribute(mma_gemm<128, false>, cudaFuncAttributeMaxDynamicSharedMemorySize, SM128_L0);
    cudaFuncSetAttribute(mma_gemm<128, true>,  cudaFuncAttributeMaxDynamicSharedMemorySize, SM128_P);
    cudaFuncSetAttribute(mma_gemm<64,  true>,  cudaFuncAttributeMaxDynamicSharedMemorySize, SM64_P);

    const int T = 256;
    const int GGRID = 296;   // 2 CTAs/SM
    const int AGRID = 1184;

    // CSR build + norms
    zero_kernel<<<(NN + T - 1) / T, T>>>();
    hist_kernel<<<(NE + T - 1) / T, T>>>(src, dst);
    scan1_kernel<<<NBLK_SCAN, 256>>>();
    scan2_kernel<<<1, 256>>>();
    scan3_kernel<<<(NN + T - 1) / T, T>>>();
    place_kernel<<<(NE + T - 1) / T, T>>>(src, dst);

    // layer 0
    mma_gemm<128, false><<<GGRID, T, SM128_L0>>>(feat, W0);
    agg_kernel<128, false><<<AGRID, T>>>(b0, nullptr);

    // layer 1
    mma_gemm<128, true><<<GGRID, T, SM128_P>>>(nullptr, W1);
    agg_kernel<128, false><<<AGRID, T>>>(b1, nullptr);

    // layer 2 (64-wide)
    mma_gemm<64, true><<<GGRID, T, SM64_P>>>(nullptr, W2);
    agg_kernel<64, true><<<AGRID, T>>>(b2, out);
}

// round 16
// speedup vs baseline: 1.1773x; 1.0767x over previous
#include <cuda_runtime.h>
#include <cuda_fp16.h>
#include <cstdint>
#include <cstddef>

#define NN 170000
#define NE 1200000
#define NBLK_SCAN 167        // ceil(NN / 1024)

// ---------------- device scratch (allocation-free) ----------------
__device__ __half g_G[(size_t)NN * 128];  // GEMM output (fp16)
__device__ __half g_H[(size_t)NN * 128];  // GEMM A source (fp16)
__device__ int    g_deg_out[NN];
__device__ int    g_cnt[NN];
__device__ int    g_off[NN];              // consumed destructively by place_kernel
__device__ int2   g_meta[NN];             // {offset, count} (preserved copy)
__device__ int    g_bsum[NBLK_SCAN];
__device__ float  g_norm_out[NN];
__device__ float  g_norm_in[NN];
__device__ int    g_csr_src[NE];

// ---------------- CSR build ----------------
__global__ void zero_kernel() {
    int i = blockIdx.x * blockDim.x + threadIdx.x;
    if (i < NN) { g_deg_out[i] = 0; g_cnt[i] = 0; }
}

__global__ void hist_kernel(const int* __restrict__ src, const int* __restrict__ dst) {
    int e = blockIdx.x * blockDim.x + threadIdx.x;
    if (e < NE) {
        atomicAdd(&g_deg_out[src[e]], 1);
        atomicAdd(&g_cnt[dst[e]], 1);
    }
}

__global__ void scan1_kernel() {
    __shared__ int sh[256];
    const int t = threadIdx.x;
    const int base = blockIdx.x * 1024 + t * 4;
    int c0 = 0, c1 = 0, c2 = 0, c3 = 0;
    if (base + 3 < NN) {
        int4 v = *reinterpret_cast<const int4*>(&g_cnt[base]);
        c0 = v.x; c1 = v.y; c2 = v.z; c3 = v.w;
    } else {
        if (base     < NN) c0 = g_cnt[base];
        if (base + 1 < NN) c1 = g_cnt[base + 1];
        if (base + 2 < NN) c2 = g_cnt[base + 2];
        if (base + 3 < NN) c3 = g_cnt[base + 3];
    }
    const int mysum = c0 + c1 + c2 + c3;
    sh[t] = mysum;
    __syncthreads();
    for (int off = 1; off < 256; off <<= 1) {
        int v = (t >= off) ? sh[t - off] : 0;
        __syncthreads();
        sh[t] += v;
        __syncthreads();
    }
    const int excl = sh[t] - mysum;
    if (t == 255) g_bsum[blockIdx.x] = sh[255];
    if (base     < NN) g_off[base]     = excl;
    if (base + 1 < NN) g_off[base + 1] = excl + c0;
    if (base + 2 < NN) g_off[base + 2] = excl + c0 + c1;
    if (base + 3 < NN) g_off[base + 3] = excl + c0 + c1 + c2;
}

__global__ void scan2_kernel() {
    __shared__ int sh[256];
    const int t = threadIdx.x;
    int v = (t < NBLK_SCAN) ? g_bsum[t] : 0;
    sh[t] = v;
    __syncthreads();
    for (int off = 1; off < 256; off <<= 1) {
        int u = (t >= off) ? sh[t - off] : 0;
        __syncthreads();
        sh[t] += u;
        __syncthreads();
    }
    if (t < NBLK_SCAN) g_bsum[t] = sh[t] - v;
}

// offsets + meta + norms
__global__ void scan3_kernel() {
    int i = blockIdx.x * blockDim.x + threadIdx.x;
    if (i < NN) {
        const int off = g_off[i] + g_bsum[i >> 10];
        g_off[i] = off;
        const int cnt = g_cnt[i];
        g_meta[i] = make_int2(off, cnt);
        int din  = cnt;          if (din  < 1) din  = 1;
        int dout = g_deg_out[i]; if (dout < 1) dout = 1;
        g_norm_in[i]  = rsqrtf((float)din);
        g_norm_out[i] = rsqrtf((float)dout);
    }
}

// destructive placement: g_off[d] is the running fill cursor (meta keeps the base)
__global__ void place_kernel(const int* __restrict__ src, const int* __restrict__ dst) {
    int e = blockIdx.x * blockDim.x + threadIdx.x;
    if (e < NE) {
        const int d = dst[e];
        const int pos = atomicAdd(&g_off[d], 1);
        g_csr_src[pos] = src[e];
    }
}

// ---------------- mma / ldmatrix / cp.async helpers ----------------
__device__ __forceinline__ void mma_f16(float* c, const uint32_t* a, uint32_t b0, uint32_t b1) {
    asm volatile(
        "mma.sync.aligned.m16n8k16.row.col.f32.f16.f16.f32 "
        "{%0,%1,%2,%3}, {%4,%5,%6,%7}, {%8,%9}, {%0,%1,%2,%3};"
        : "+f"(c[0]), "+f"(c[1]), "+f"(c[2]), "+f"(c[3])
        : "r"(a[0]), "r"(a[1]), "r"(a[2]), "r"(a[3]), "r"(b0), "r"(b1));
}

__device__ __forceinline__ void ldsm_x4(uint32_t* r, uint32_t addr) {
    asm volatile("ldmatrix.sync.aligned.m8n8.x4.shared.b16 {%0,%1,%2,%3}, [%4];"
                 : "=r"(r[0]), "=r"(r[1]), "=r"(r[2]), "=r"(r[3]) : "r"(addr));
}

__device__ __forceinline__ void ldsm_x2(uint32_t& r0, uint32_t& r1, uint32_t addr) {
    asm volatile("ldmatrix.sync.aligned.m8n8.x2.shared.b16 {%0,%1}, [%2];"
                 : "=r"(r0), "=r"(r1) : "r"(addr));
}

__device__ __forceinline__ void cp16(uint32_t dst, const void* src) {
    asm volatile("cp.async.cg.shared.global [%0], [%1], 16;" :: "r"(dst), "l"(src));
}
__device__ __forceinline__ void cp_commit() { asm volatile("cp.async.commit_group;"); }
__device__ __forceinline__ void cp_wait1()  { asm volatile("cp.async.wait_group 1;"); }
__device__ __forceinline__ void cp_wait0()  { asm volatile("cp.async.wait_group 0;"); }

__device__ __forceinline__ uint32_t hadd2u(uint32_t a, uint32_t b) {
    __half2 r = __hadd2(*reinterpret_cast<const __half2*>(&a),
                        *reinterpret_cast<const __half2*>(&b));
    return *reinterpret_cast<uint32_t*>(&r);
}

// ---------------- tensor-core GEMM (fp16 m16n8k16 + ldmatrix) ----------------
// SRC_H=false (layer 0): cp.async fp32 staging pipeline (1 staging buffer, 2 CTAs/SM).
// SRC_H=true (layers 1,2): cp.async double-buffered fp16 bit-copy (3 CTAs/SM).
template <int OUTD, bool SRC_H>
__global__ void __launch_bounds__(256, 3) mma_gemm(const float* __restrict__ X,
                                                   const float* __restrict__ W) {
    constexpr int NF = OUTD / 32;
    constexpr int P  = 68;
    extern __shared__ uint32_t smw[];
    uint32_t* Wh = smw;                    // [OUTD][P]
    uint32_t* A0 = Wh + OUTD * P;          // [64][P]
    uint32_t* A1 = A0 + 64 * P;            // [64][P] | L0: fp32 staging
    float*    S  = reinterpret_cast<float*>(A1);  // L0: [64][128] fp32 staging (32KB)

    const int tid  = threadIdx.x;
    const int lane = tid & 31;
    const int warp = tid >> 5;
    const int mw   = warp & 1;
    const int nw   = warp >> 1;
    const int g    = lane >> 2;
    const int tg   = lane & 3;

    for (int i = tid; i < 64 * OUTD; i += 256) {
        const int kp = i / OUTD, n = i - kp * OUTD;
        const float w0 = W[(size_t)(kp * 2)     * OUTD + n];
        const float w1 = W[(size_t)(kp * 2 + 1) * OUTD + n];
        __half2 h = __floats2half2_rn(w0, w1);
        Wh[n * P + kp] = *reinterpret_cast<uint32_t*>(&h);
    }

    const uint32_t aB0 = (uint32_t)__cvta_generic_to_shared(A0);
    const uint32_t aB1 = (uint32_t)__cvta_generic_to_shared(A1);
    const uint32_t sB  = (uint32_t)__cvta_generic_to_shared(S);
    const uint32_t wBase = (uint32_t)__cvta_generic_to_shared(Wh);
    const int sel = lane >> 3;
    const int li  = lane & 7;
    uint32_t aOff[2];
#pragma unroll
    for (int mf = 0; mf < 2; mf++) {
        const int row = mw * 32 + mf * 16 + (sel & 1) * 8 + li;
        aOff[mf] = (uint32_t)((row * P + (sel >> 1) * 4) * 4);
    }
    uint32_t bAddr[NF];
#pragma unroll
    for (int nf = 0; nf < NF; nf++) {
        const int n = nw * (NF * 8) + nf * 8 + li;
        bAddr[nf] = wBase + (uint32_t)((n * P + (sel & 1) * 4) * 4);
    }

    const int ntiles = (NN + 63) / 64;

    auto compute_store = [&](uint32_t aBase, int rowbase) {
        float acc[2][NF][4];
#pragma unroll
        for (int mf = 0; mf < 2; mf++)
#pragma unroll
            for (int nf = 0; nf < NF; nf++)
#pragma unroll
                for (int j = 0; j < 4; j++) acc[mf][nf][j] = 0.f;

#pragma unroll
        for (int ks = 0; ks < 8; ks++) {
            uint32_t a[2][4];
            ldsm_x4(a[0], aBase + aOff[0] + ks * 32);
            ldsm_x4(a[1], aBase + aOff[1] + ks * 32);
            uint32_t b[NF][2];
#pragma unroll
            for (int nf = 0; nf < NF; nf++)
                ldsm_x2(b[nf][0], b[nf][1], bAddr[nf] + ks * 32);
#pragma unroll
            for (int nf = 0; nf < NF; nf++)
#pragma unroll
                for (int mf = 0; mf < 2; mf++)
                    mma_f16(acc[mf][nf], a[mf], b[nf][0], b[nf][1]);
        }

#pragma unroll
        for (int mf = 0; mf < 2; mf++) {
            const int r0 = rowbase + mw * 32 + mf * 16 + g;
#pragma unroll
            for (int nf = 0; nf < NF; nf++) {
                const int col = nw * (NF * 8) + nf * 8 + tg * 2;
                if (r0 < NN) {
                    __half2 h = __floats2half2_rn(acc[mf][nf][0], acc[mf][nf][1]);
                    *reinterpret_cast<__half2*>(&g_G[(size_t)r0 * OUTD + col]) = h;
                }
                if (r0 + 8 < NN) {
                    __half2 h = __floats2half2_rn(acc[mf][nf][2], acc[mf][nf][3]);
                    *reinterpret_cast<__half2*>(&g_G[(size_t)(r0 + 8) * OUTD + col]) = h;
                }
            }
        }
    };

    if (SRC_H) {
        auto prefetch = [&](int tile, uint32_t bufBase) {
#pragma unroll
            for (int j = 0; j < 4; j++) {
                const int id = tid + j * 256;
                const int r = id >> 4, c16 = id & 15;
                int row = tile * 64 + r;
                if (row >= NN) row = NN - 1;
                cp16(bufBase + (uint32_t)((r * P + c16 * 4) * 4),
                     g_H + (size_t)row * 128 + c16 * 8);
            }
        };

        int t = blockIdx.x;
        if (t < ntiles) prefetch(t, aB0);
        cp_commit();
        int parity = 0;
        for (; t < ntiles; t += gridDim.x) {
            const int tn = t + gridDim.x;
            if (tn < ntiles) prefetch(tn, parity ? aB0 : aB1);
            cp_commit();
            cp_wait1();
            __syncthreads();
            compute_store(parity ? aB1 : aB0, t * 64);
            __syncthreads();
            parity ^= 1;
        }
    } else {
        auto stage = [&](int tile) {
#pragma unroll
            for (int j = 0; j < 8; j++) {
                const int id = tid + j * 256;
                const int r = id >> 5, c16 = id & 31;
                int row = tile * 64 + r;
                if (row >= NN) row = NN - 1;
                cp16(sB + (uint32_t)((r * 128 + c16 * 4) * 4),
                     X + (size_t)row * 128 + c16 * 4);
            }
        };

        int t = blockIdx.x;
        if (t < ntiles) stage(t);
        cp_commit();
        for (; t < ntiles; t += gridDim.x) {
            cp_wait0();
            __syncthreads();
            const int rowbase = t * 64;
            for (int i = tid; i < 64 * 32; i += 256) {
                const int r = i >> 5, c4 = i & 31;
                const int row = rowbase + r;
                uint32_t w0 = 0, w1 = 0;
                if (row < NN) {
                    const float4 v = *reinterpret_cast<const float4*>(&S[r * 128 + c4 * 4]);
                    const float no = g_norm_out[row];
                    __half2 h0 = __floats2half2_rn(v.x * no, v.y * no);
                    __half2 h1 = __floats2half2_rn(v.z * no, v.w * no);
                    w0 = *reinterpret_cast<uint32_t*>(&h0);
                    w1 = *reinterpret_cast<uint32_t*>(&h1);
                }
                A0[r * P + c4 * 2]     = w0;
                A0[r * P + c4 * 2 + 1] = w1;
            }
            __syncthreads();
            const int tn = t + gridDim.x;
            if (tn < ntiles) stage(tn);
            cp_commit();
            compute_store(aB0, rowbase);
            __syncthreads();
        }
    }
}

// ---------------- CSR gather aggregation: half-warp per node, node-pipelined ----------------
// Per iteration: prefetch next node's meta early; after current accumulation, prefetch
// next node's first 8 indices (meta has arrived); then epilogue. HADD2 pairwise reduce.
template <int WIDTH, bool FINAL>
__global__ void __launch_bounds__(256) agg_kernel(const float* __restrict__ bias,
                                                  float* __restrict__ outp) {
    const int l   = threadIdx.x & 15;
    int n = (blockIdx.x * blockDim.x + threadIdx.x) >> 4;
    const int nhw = (gridDim.x * blockDim.x) >> 4;
    if (n >= NN) return;

    int2 m = __ldg(&g_meta[n]);
    int cidx[8];
#pragma unroll
    for (int i = 0; i < 8; i++)
        cidx[i] = __ldg(&g_csr_src[(i < m.y) ? (m.x + i) : 0]);

    while (true) {
        const int nn = n + nhw;
        const bool has_next = nn < NN;
        int2 m_nxt = make_int2(0, 0);
        if (has_next) m_nxt = __ldg(&g_meta[nn]);   // independent: hidden under row loads

        const int deg = m.y;
        const int end = m.x + deg;

        if (WIDTH == 128) {
            float accA[8] = {0,0,0,0,0,0,0,0};
            float accB[8] = {0,0,0,0,0,0,0,0};
            if (deg > 0) {
                // batch 0: preloaded indices, predicated
                {
                    uint4 raw[8];
#pragma unroll
                    for (int i = 0; i < 8; i++) {
                        uint4 r = reinterpret_cast<const uint4*>(g_G + (size_t)cidx[i] * 128)[l];
                        const bool v = i < deg;
                        raw[i].x = v ? r.x : 0u;
                        raw[i].y = v ? r.y : 0u;
                        raw[i].z = v ? r.z : 0u;
                        raw[i].w = v ? r.w : 0u;
                    }
#pragma unroll
                    for (int p = 0; p < 4; p++) {
                        uint4 h;
                        h.x = hadd2u(raw[2*p].x, raw[2*p+1].x);
                        h.y = hadd2u(raw[2*p].y, raw[2*p+1].y);
                        h.z = hadd2u(raw[2*p].z, raw[2*p+1].z);
                        h.w = hadd2u(raw[2*p].w, raw[2*p+1].w);
                        float* acc = (p & 1) ? accB : accA;
                        const float2 p0 = __half22float2(*reinterpret_cast<const __half2*>(&h.x));
                        const float2 p1 = __half22float2(*reinterpret_cast<const __half2*>(&h.y));
                        const float2 p2 = __half22float2(*reinterpret_cast<const __half2*>(&h.z));
                        const float2 p3 = __half22float2(*reinterpret_cast<const __half2*>(&h.w));
                        acc[0] += p0.x; acc[1] += p0.y; acc[2] += p1.x; acc[3] += p1.y;
                        acc[4] += p2.x; acc[5] += p2.y; acc[6] += p3.x; acc[7] += p3.y;
                    }
                }
                // remaining batches
                int e = m.x + 8;
                for (; e + 8 <= end; e += 8) {
                    uint4 raw[8];
#pragma unroll
                    for (int i = 0; i < 8; i++) {
                        const int s = __ldg(&g_csr_src[e + i]);
                        raw[i] = reinterpret_cast<const uint4*>(g_G + (size_t)s * 128)[l];
                    }
#pragma unroll
                    for (int p = 0; p < 4; p++) {
                        uint4 h;
                        h.x = hadd2u(raw[2*p].x, raw[2*p+1].x);
                        h.y = hadd2u(raw[2*p].y, raw[2*p+1].y);
                        h.z = hadd2u(raw[2*p].z, raw[2*p+1].z);
                        h.w = hadd2u(raw[2*p].w, raw[2*p+1].w);
                        float* acc = (p & 1) ? accB : accA;
                        const float2 p0 = __half22float2(*reinterpret_cast<const __half2*>(&h.x));
                        const float2 p1 = __half22float2(*reinterpret_cast<const __half2*>(&h.y));
                        const float2 p2 = __half22float2(*reinterpret_cast<const __half2*>(&h.z));
                        const float2 p3 = __half22float2(*reinterpret_cast<const __half2*>(&h.w));
                        acc[0] += p0.x; acc[1] += p0.y; acc[2] += p1.x; acc[3] += p1.y;
                        acc[4] += p2.x; acc[5] += p2.y; acc[6] += p3.x; acc[7] += p3.y;
                    }
                }
                if (e < end) {
                    uint4 raw[8];
#pragma unroll
                    for (int i = 0; i < 8; i++) {
                        const int ee = e + i;
                        const bool v = ee < end;
                        const int s = __ldg(&g_csr_src[v ? ee : m.x]);
                        uint4 r = reinterpret_cast<const uint4*>(g_G + (size_t)s * 128)[l];
                        raw[i].x = v ? r.x : 0u;
                        raw[i].y = v ? r.y : 0u;
                        raw[i].z = v ? r.z : 0u;
                        raw[i].w = v ? r.w : 0u;
                    }
#pragma unroll
                    for (int p = 0; p < 4; p++) {
                        uint4 h;
                        h.x = hadd2u(raw[2*p].x, raw[2*p+1].x);
                        h.y = hadd2u(raw[2*p].y, raw[2*p+1].y);
                        h.z = hadd2u(raw[2*p].z, raw[2*p+1].z);
                        h.w = hadd2u(raw[2*p].w, raw[2*p+1].w);
                        float* acc = (p & 1) ? accB : accA;
                        const float2 p0 = __half22float2(*reinterpret_cast<const __half2*>(&h.x));
                        const float2 p1 = __half22float2(*reinterpret_cast<const __half2*>(&h.y));
                        const float2 p2 = __half22float2(*reinterpret_cast<const __half2*>(&h.z));
                        const float2 p3 = __half22float2(*reinterpret_cast<const __half2*>(&h.w));
                        acc[0] += p0.x; acc[1] += p0.y; acc[2] += p1.x; acc[3] += p1.y;
                        acc[4] += p2.x; acc[5] += p2.y; acc[6] += p3.x; acc[7] += p3.y;
                    }
                }
            }

            // prefetch next node's first indices (meta arrived by now)
            if (has_next) {
#pragma unroll
                for (int i = 0; i < 8; i++)
                    cidx[i] = __ldg(&g_csr_src[(i < m_nxt.y) ? (m_nxt.x + i) : 0]);
            }

            const float ni = g_norm_in[n];
            const float no = g_norm_out[n];
            const float4 bb0 = reinterpret_cast<const float4*>(bias)[l * 2];
            const float4 bb1 = reinterpret_cast<const float4*>(bias)[l * 2 + 1];
            float r0 = fmaxf(fmaf(accA[0] + accB[0], ni, bb0.x), 0.f) * no;
            float r1 = fmaxf(fmaf(accA[1] + accB[1], ni, bb0.y), 0.f) * no;
            float r2 = fmaxf(fmaf(accA[2] + accB[2], ni, bb0.z), 0.f) * no;
            float r3 = fmaxf(fmaf(accA[3] + accB[3], ni, bb0.w), 0.f) * no;
            float r4 = fmaxf(fmaf(accA[4] + accB[4], ni, bb1.x), 0.f) * no;
            float r5 = fmaxf(fmaf(accA[5] + accB[5], ni, bb1.y), 0.f) * no;
            float r6 = fmaxf(fmaf(accA[6] + accB[6], ni, bb1.z), 0.f) * no;
            float r7 = fmaxf(fmaf(accA[7] + accB[7], ni, bb1.w), 0.f) * no;
            __half2 h0 = __floats2half2_rn(r0, r1);
            __half2 h1 = __floats2half2_rn(r2, r3);
            __half2 h2 = __floats2half2_rn(r4, r5);
            __half2 h3 = __floats2half2_rn(r6, r7);
            uint4 o;
            o.x = *reinterpret_cast<uint32_t*>(&h0);
            o.y = *reinterpret_cast<uint32_t*>(&h1);
            o.z = *reinterpret_cast<uint32_t*>(&h2);
            o.w = *reinterpret_cast<uint32_t*>(&h3);
            reinterpret_cast<uint4*>(g_H + (size_t)n * 128)[l] = o;
        } else {
            float accA[4] = {0,0,0,0};
            float accB[4] = {0,0,0,0};
            if (deg > 0) {
                {
                    uint2 raw[8];
#pragma unroll
                    for (int i = 0; i < 8; i++) {
                        uint2 r = reinterpret_cast<const uint2*>(g_G + (size_t)cidx[i] * 64)[l];
                        const bool v = i < deg;
                        raw[i].x = v ? r.x : 0u;
                        raw[i].y = v ? r.y : 0u;
                    }
#pragma unroll
                    for (int p = 0; p < 4; p++) {
                        uint2 h;
                        h.x = hadd2u(raw[2*p].x, raw[2*p+1].x);
                        h.y = hadd2u(raw[2*p].y, raw[2*p+1].y);
                        float* acc = (p & 1) ? accB : accA;
                        const float2 p0 = __half22float2(*reinterpret_cast<const __half2*>(&h.x));
                        const float2 p1 = __half22float2(*reinterpret_cast<const __half2*>(&h.y));
                        acc[0] += p0.x; acc[1] += p0.y; acc[2] += p1.x; acc[3] += p1.y;
                    }
                }
                int e = m.x + 8;
                for (; e + 8 <= end; e += 8) {
                    uint2 raw[8];
#pragma unroll
                    for (int i = 0; i < 8; i++) {
                        const int s = __ldg(&g_csr_src[e + i]);
                        raw[i] = reinterpret_cast<const uint2*>(g_G + (size_t)s * 64)[l];
                    }
#pragma unroll
                    for (int p = 0; p < 4; p++) {
                        uint2 h;
                        h.x = hadd2u(raw[2*p].x, raw[2*p+1].x);
                        h.y = hadd2u(raw[2*p].y, raw[2*p+1].y);
                        float* acc = (p & 1) ? accB : accA;
                        const float2 p0 = __half22float2(*reinterpret_cast<const __half2*>(&h.x));
                        const float2 p1 = __half22float2(*reinterpret_cast<const __half2*>(&h.y));
                        acc[0] += p0.x; acc[1] += p0.y; acc[2] += p1.x; acc[3] += p1.y;
                    }
                }
                if (e < end) {
                    uint2 raw[8];
#pragma unroll
                    for (int i = 0; i < 8; i++) {
                        const int ee = e + i;
                        const bool v = ee < end;
                        const int s = __ldg(&g_csr_src[v ? ee : m.x]);
                        uint2 r = reinterpret_cast<const uint2*>(g_G + (size_t)s * 64)[l];
                        raw[i].x = v ? r.x : 0u;
                        raw[i].y = v ? r.y : 0u;
                    }
#pragma unroll
                    for (int p = 0; p < 4; p++) {
                        uint2 h;
                        h.x = hadd2u(raw[2*p].x, raw[2*p+1].x);
                        h.y = hadd2u(raw[2*p].y, raw[2*p+1].y);
                        float* acc = (p & 1) ? accB : accA;
                        const float2 p0 = __half22float2(*reinterpret_cast<const __half2*>(&h.x));
                        const float2 p1 = __half22float2(*reinterpret_cast<const __half2*>(&h.y));
                        acc[0] += p0.x; acc[1] += p0.y; acc[2] += p1.x; acc[3] += p1.y;
                    }
                }
            }

            if (has_next) {
#pragma unroll
                for (int i = 0; i < 8; i++)
                    cidx[i] = __ldg(&g_csr_src[(i < m_nxt.y) ? (m_nxt.x + i) : 0]);
            }

            const float ni = g_norm_in[n];
            const float4 bb = reinterpret_cast<const float4*>(bias)[l];
            float4 o;
            o.x = fmaf(accA[0] + accB[0], ni, bb.x);
            o.y = fmaf(accA[1] + accB[1], ni, bb.y);
            o.z = fmaf(accA[2] + accB[2], ni, bb.z);
            o.w = fmaf(accA[3] + accB[3], ni, bb.w);
            reinterpret_cast<float4*>(outp + (size_t)n * 64)[l] = o;
        }

        if (!has_next) break;
        n = nn;
        m = m_nxt;
    }
}

// ---------------- launch ----------------
extern "C" void kernel_launch(void* const* d_in, const int* in_sizes, int n_in,
                              void* d_out, int out_size) {
    const float* feat = (const float*)d_in[0];
    const int*   src  = (const int*)d_in[1];
    const int*   dst  = (const int*)d_in[2];
    const float* W0   = (const float*)d_in[3];
    const float* b0   = (const float*)d_in[4];
    const float* W1   = (const float*)d_in[5];
    const float* b1   = (const float*)d_in[6];
    const float* W2   = (const float*)d_in[7];
    const float* b2   = (const float*)d_in[8];
    float* out = (float*)d_out;

    const int SM128_L0 = (128 * 68 + 64 * 68) * 4 + 64 * 128 * 4;  // 85 KB  (2 CTAs/SM)
    const int SM128_P  = (128 * 68 + 2 * 64 * 68) * 4;             // 69632 B (3 CTAs/SM)
    const int SM64_P   = (64 * 68 + 2 * 64 * 68) * 4;              // 52224 B
    cudaFuncSetAttribute(mma_gemm<128, false>, cudaFuncAttributeMaxDynamicSharedMemorySize, SM128_L0);
    cudaFuncSetAttribute(mma_gemm<128, true>,  cudaFuncAttributeMaxDynamicSharedMemorySize, SM128_P);
    cudaFuncSetAttribute(mma_gemm<64,  true>,  cudaFuncAttributeMaxDynamicSharedMemorySize, SM64_P);

    const int T = 256;
    const int GGRID_L0 = 296;   // 2 CTAs/SM (85KB smem)
    const int GGRID_P  = 444;   // 3 CTAs/SM
    const int AGRID = 1184;

    // CSR build + norms
    zero_kernel<<<(NN + T - 1) / T, T>>>();
    hist_kernel<<<(NE + T - 1) / T, T>>>(src, dst);
    scan1_kernel<<<NBLK_SCAN, 256>>>();
    scan2_kernel<<<1, 256>>>();
    scan3_kernel<<<(NN + T - 1) / T, T>>>();
    place_kernel<<<(NE + T - 1) / T, T>>>(src, dst);

    // layer 0
    mma_gemm<128, false><<<GGRID_L0, T, SM128_L0>>>(feat, W0);
    agg_kernel<128, false><<<AGRID, T>>>(b0, nullptr);

    // layer 1
    mma_gemm<128, true><<<GGRID_P, T, SM128_P>>>(nullptr, W1);
    agg_kernel<128, false><<<AGRID, T>>>(b1, nullptr);

    // layer 2 (64-wide)
    mma_gemm<64, true><<<GGRID_P, T, SM64_P>>>(nullptr, W2);
    agg_kernel<64, true><<<AGRID, T>>>(b2, out);
}